// round 12
// baseline (speedup 1.0000x reference)
#include <cuda_runtime.h>
#include <cuda_bf16.h>
#include <math.h>

// ---------------- problem constants ----------------
#define Bn      2
#define Tn      16384
#define Ln      64
#define HOPn    256
#define INCH    101
#define INNERC  128
#define CONDC   81
#define KHC     64
#define COUTC   256
#define KCHn    491520          // 5*128*256*3
#define BCHn    1280            // 256*5
// padded packed-weight slice: 192 j-rows x 264 u32 (256 data + 8 pad)
#define WROW    264
#define SLICE_U32 50688         // 192*264 u32 per plane per slice

// ---------------- numeric helpers ----------------
__device__ __forceinline__ unsigned f2tf(float f) {
    unsigned u; asm("cvt.rna.tf32.f32 %0, %1;" : "=r"(u) : "f"(f)); return u;
}
__device__ __forceinline__ void split_tf(float v, float& hi, float& lo) {
    hi = __uint_as_float(f2tf(v));
    lo = __uint_as_float(f2tf(v - hi));
}
__device__ __forceinline__ void split_bf(float v, unsigned& h, unsigned& l) {
    __nv_bfloat16 hb = __float2bfloat16_rn(v);
    float hf = __bfloat162float(hb);
    __nv_bfloat16 lb = __float2bfloat16_rn(v - hf);
    h = (unsigned)__bfloat16_as_ushort(hb);
    l = (unsigned)__bfloat16_as_ushort(lb);
}
__device__ __forceinline__ void mma_tf32(float* d, const unsigned* a, const unsigned* b) {
    asm("mma.sync.aligned.m16n8k8.row.col.f32.tf32.tf32.f32 "
        "{%0,%1,%2,%3}, {%4,%5,%6,%7}, {%8,%9}, {%0,%1,%2,%3};"
        : "+f"(d[0]), "+f"(d[1]), "+f"(d[2]), "+f"(d[3])
        : "r"(a[0]), "r"(a[1]), "r"(a[2]), "r"(a[3]), "r"(b[0]), "r"(b[1]));
}
__device__ __forceinline__ void mma_bf16(float* d, const unsigned* a, const unsigned* b) {
    asm("mma.sync.aligned.m16n8k16.row.col.f32.bf16.bf16.f32 "
        "{%0,%1,%2,%3}, {%4,%5,%6,%7}, {%8,%9}, {%0,%1,%2,%3};"
        : "+f"(d[0]), "+f"(d[1]), "+f"(d[2]), "+f"(d[3])
        : "r"(a[0]), "r"(a[1]), "r"(a[2]), "r"(a[3]), "r"(b[0]), "r"(b[1]));
}
// bulk-TMA 1D load + mbarrier
__device__ __forceinline__ void bulk_ld(unsigned dst_smem, const void* gsrc,
                                        unsigned bytes, unsigned mbar) {
    asm volatile("cp.async.bulk.shared::cta.global.mbarrier::complete_tx::bytes "
                 "[%0], [%1], %2, [%3];"
                 :: "r"(dst_smem), "l"(gsrc), "r"(bytes), "r"(mbar) : "memory");
}
__device__ __forceinline__ void mbar_init(unsigned mbar, unsigned cnt) {
    asm volatile("mbarrier.init.shared.b64 [%0], %1;" :: "r"(mbar), "r"(cnt) : "memory");
}
__device__ __forceinline__ void mbar_expect(unsigned mbar, unsigned bytes) {
    asm volatile("mbarrier.arrive.expect_tx.shared.b64 _, [%0], %1;"
                 :: "r"(mbar), "r"(bytes) : "memory");
}
__device__ __forceinline__ void mbar_wait(unsigned mbar, unsigned parity) {
    asm volatile(
        "{\n\t.reg .pred P1;\n\t"
        "WAIT_LOOP_%=:\n\t"
        "mbarrier.try_wait.parity.acquire.cta.shared::cta.b64 P1, [%0], %1, 0x989680;\n\t"
        "@P1 bra.uni WAIT_DONE_%=;\n\t"
        "bra.uni WAIT_LOOP_%=;\n\t"
        "WAIT_DONE_%=:\n\t}"
        :: "r"(mbar), "r"(parity) : "memory");
}

// ---------------- scratch ----------------
__device__ float    g_h [Bn*INNERC*Tn];
__device__ float    g_x1[Bn*INNERC*Tn];
__device__ float    g_y1[Bn*INNERC*Tn];
__device__ unsigned g_hph[Bn*64*Tn], g_hpl[Bn*64*Tn];
__device__ unsigned g_xph[Bn*64*Tn], g_xpl[Bn*64*Tn];
__device__ unsigned g_yph[Bn*64*Tn], g_ypl[Bn*64*Tn];
__device__ float    g_hc[2*Bn*KHC*Ln];
__device__ float    g_bs[2*Bn*BCHn*Ln];
__device__ float    g_Bth[2*64*128], g_Btl[2*64*128];
// padded bf16 hi/lo planes: [slice=nl*128+b*64+l][j=tap*64+ip][264]
__device__ unsigned g_Wh[(size_t)1280*SLICE_U32];
__device__ unsigned g_Wl[(size_t)1280*SLICE_U32];

// =====================================================================
// 1) fc
// =====================================================================
__global__ void __launch_bounds__(128)
fc_kernel(const float* __restrict__ x,
          const float* __restrict__ W,
          const float* __restrict__ bias,
          float* __restrict__ out,
          unsigned* __restrict__ outh,
          unsigned* __restrict__ outl)
{
    __shared__ float sx[INCH*32];
    __shared__ float sW[128*33];
    const int b  = blockIdx.y;
    const int t0 = blockIdx.x * 32;
    const int tid = threadIdx.x;

    for (int p = tid; p < INCH*32; p += 128) {
        int c = p >> 5, j = p & 31;
        sx[p] = x[((size_t)(b*INCH + c))*Tn + t0 + j];
    }
    float acc[32];
    float bv = bias[tid];
#pragma unroll
    for (int j = 0; j < 32; j++) acc[j] = bv;

    for (int c0 = 0; c0 < INCH; c0 += 32) {
        int cmax = (INCH - c0) < 32 ? (INCH - c0) : 32;
        __syncthreads();
        for (int p = tid; p < 128*32; p += 128) {
            int o = p >> 5, cl = p & 31;
            if (cl < cmax) sW[o*33 + cl] = W[o*INCH + c0 + cl];
        }
        __syncthreads();
        for (int cl = 0; cl < cmax; cl++) {
            float w = sW[tid*33 + cl];
            const float* xr = &sx[(c0 + cl)*32];
#pragma unroll
            for (int j = 0; j < 32; j++) acc[j] += w * xr[j];
        }
    }
    float* o = &out[((size_t)(b*INNERC + tid))*Tn + t0];
#pragma unroll
    for (int j = 0; j < 32; j++) o[j] = acc[j];

    __syncthreads();
#pragma unroll
    for (int j = 0; j < 32; j++) sW[tid*33 + j] = acc[j];
    __syncthreads();
    for (int p = tid; p < 64*32; p += 128) {
        int jg = p >> 5, t = p & 31;
        unsigned h0,l0,h1,l1;
        split_bf(sW[(2*jg)*33 + t],   h0, l0);
        split_bf(sW[(2*jg+1)*33 + t], h1, l1);
        size_t idx = ((size_t)(b*64 + jg))*Tn + t0 + t;
        outh[idx] = h0 | (h1 << 16);
        outl[idx] = l0 | (l1 << 16);
    }
}

// =====================================================================
// 2) kernel predictor
// =====================================================================
__global__ void __launch_bounds__(256)
predictor_kernel(const float* __restrict__ cond,
                 const float* __restrict__ iW, const float* __restrict__ ib,
                 const float* __restrict__ r1W, const float* __restrict__ r1b,
                 const float* __restrict__ r2W, const float* __restrict__ r2b,
                 const float* __restrict__ bW,  const float* __restrict__ bb,
                 float* __restrict__ hc_out, float* __restrict__ bias_out,
                 float* __restrict__ Bth, float* __restrict__ Btl)
{
    __shared__ float bufc[CONDC*Ln];
    __shared__ float bufh[KHC*Ln];
    const int nb = blockIdx.x;
    const int n  = nb >> 1;
    const int b  = nb & 1;
    const int tid = threadIdx.x;
    const int NT = 256;

    for (int p = tid; p < CONDC*Ln; p += NT) bufc[p] = cond[b*CONDC*Ln + p];
    __syncthreads();

    for (int idx = tid; idx < KHC*Ln; idx += NT) {
        int kh = idx >> 6, l = idx & 63;
        float a = ib[n*KHC + kh];
        const float* wrow = &iW[(size_t)(n*KHC + kh)*CONDC*5];
        for (int cc = 0; cc < CONDC; cc++) {
#pragma unroll
            for (int k = 0; k < 5; k++) {
                int ll = l + k - 2;
                if (ll >= 0 && ll < Ln) a += bufc[cc*Ln + ll] * wrow[cc*5 + k];
            }
        }
        bufh[idx] = a >= 0.f ? a : 0.1f*a;
    }
    __syncthreads();

    for (int idx = tid; idx < KHC*Ln; idx += NT) {
        int o = idx >> 6, l = idx & 63;
        float a = r1b[n*KHC + o];
        const float* wr = &r1W[(size_t)(n*KHC + o)*KHC];
        for (int i = 0; i < KHC; i++) a += wr[i] * bufh[i*Ln + l];
        bufc[idx] = a >= 0.f ? a : 0.1f*a;
    }
    __syncthreads();

    for (int idx = tid; idx < KHC*Ln; idx += NT) {
        int o = idx >> 6, l = idx & 63;
        float a = r2b[n*KHC + o];
        const float* wr = &r2W[(size_t)(n*KHC + o)*KHC];
        for (int i = 0; i < KHC; i++) a += wr[i] * bufc[i*Ln + l];
        bufh[idx] = bufh[idx] + a;
    }
    __syncthreads();

    for (int idx = tid; idx < KHC*Ln; idx += NT) hc_out[nb*KHC*Ln + idx] = bufh[idx];

    for (int idx = tid; idx < KHC*Ln; idx += NT) {
        int k = idx >> 6, l = idx & 63;
        float h, lo; split_tf(bufh[k*Ln + l], h, lo);
        int col = b*64 + l;
        Bth[(n*64 + k)*128 + col] = h;
        Btl[(n*64 + k)*128 + col] = lo;
    }

    for (int idx = tid; idx < BCHn*Ln; idx += NT) {
        int j = idx >> 6, l = idx & 63;
        float a = bb[n*BCHn + j];
        const float* wr = &bW[(size_t)(n*BCHn + j)*KHC];
        for (int i = 0; i < KHC; i++) a += wr[i] * bufh[i*Ln + l];
        bias_out[(size_t)nb*BCHn*Ln + idx] = a;
    }
}

// =====================================================================
// 3) weight GEMM per slab nl
// =====================================================================
#define WG_SA 4352   // 64*68
#define WG_SB 8704   // 64*136
#define WG_SMEM ((2*WG_SA + 2*WG_SB) * (int)sizeof(float))   // 104448 B

__global__ void __launch_bounds__(256)
wgemm_kernel(const float* __restrict__ kW,
             const float* __restrict__ kb,
             const float* __restrict__ Bth,
             const float* __restrict__ Btl,
             unsigned* __restrict__ gWh,
             unsigned* __restrict__ gWl,
             int nl)
{
    extern __shared__ float wsm[];
    float* sAh = wsm;
    float* sAl = wsm + WG_SA;
    float* sBh = wsm + 2*WG_SA;
    float* sBl = wsm + 2*WG_SA + WG_SB;

    const int tid  = threadIdx.x;
    const int bx   = blockIdx.x;
    const int n    = nl / 5, layer = nl % 5;
    const int ip   = bx / 12;
    const int rem  = bx % 12;
    const int tap  = rem >> 2;
    const int o0   = (rem & 3) * 64;

    const size_t nbase = (size_t)n*KCHn + (size_t)layer*(384*256);
    const size_t srcrowE = nbase + (size_t)(2*ip)*768 + (size_t)o0*3 + tap;

    {
        const float4* srcH4 = (const float4*)(Bth + n*8192);
        const float4* srcL4 = (const float4*)(Btl + n*8192);
        for (int p4 = tid; p4 < 64*32; p4 += 256) {
            int k = p4 >> 5, c4 = p4 & 31;
            *(float4*)(sBh + k*136 + c4*4) = srcH4[p4];
            *(float4*)(sBl + k*136 + c4*4) = srcL4[p4];
        }
    }

    const int wid  = tid >> 5;
    const int lane = tid & 31;
    const int obase = (wid >> 2) * 32;
    const int cbase = (wid & 3) * 32;
    const int lr = lane >> 2;
    const int lc = lane & 3;

    float d[2][2][4][4];
#pragma unroll
    for (int p = 0; p < 2; p++)
#pragma unroll
        for (int mt = 0; mt < 2; mt++)
#pragma unroll
            for (int nt = 0; nt < 4; nt++)
#pragma unroll
                for (int q = 0; q < 4; q++) d[p][mt][nt][q] = 0.f;

    const float4* kW4 = (const float4*)kW;
#pragma unroll
    for (int par = 0; par < 2; par++) {
        __syncthreads();
        const size_t srcrow = srcrowE + (size_t)par*768;
        for (int p4 = tid; p4 < 64*16; p4 += 256) {
            int r = p4 >> 4, kq = p4 & 15;
            float4 v = kW4[srcrow*16 + (size_t)r*48 + kq];
            float h0,l0,h1,l1,h2,l2,h3,l3;
            split_tf(v.x,h0,l0); split_tf(v.y,h1,l1);
            split_tf(v.z,h2,l2); split_tf(v.w,h3,l3);
            float* dh = sAh + r*68 + kq*4;
            float* dl = sAl + r*68 + kq*4;
            dh[0]=h0; dh[1]=h1; dh[2]=h2; dh[3]=h3;
            dl[0]=l0; dl[1]=l1; dl[2]=l2; dl[3]=l3;
        }
        __syncthreads();

#pragma unroll
        for (int ks = 0; ks < 8; ks++) {
            unsigned bh[4][2], bl[4][2];
            const float* bpH = sBh + (ks*8 + lc)*136 + cbase + lr;
            const float* bpL = sBl + (ks*8 + lc)*136 + cbase + lr;
#pragma unroll
            for (int nt = 0; nt < 4; nt++) {
                bh[nt][0] = __float_as_uint(bpH[nt*8]);
                bh[nt][1] = __float_as_uint(bpH[4*136 + nt*8]);
                bl[nt][0] = __float_as_uint(bpL[nt*8]);
                bl[nt][1] = __float_as_uint(bpL[4*136 + nt*8]);
            }
#pragma unroll
            for (int mt = 0; mt < 2; mt++) {
                const int ap = (obase + mt*16 + lr)*68 + ks*8 + lc;
                unsigned ah[4], al[4];
                ah[0] = __float_as_uint(sAh[ap]);
                ah[1] = __float_as_uint(sAh[ap + 8*68]);
                ah[2] = __float_as_uint(sAh[ap + 4]);
                ah[3] = __float_as_uint(sAh[ap + 8*68 + 4]);
                al[0] = __float_as_uint(sAl[ap]);
                al[1] = __float_as_uint(sAl[ap + 8*68]);
                al[2] = __float_as_uint(sAl[ap + 4]);
                al[3] = __float_as_uint(sAl[ap + 8*68 + 4]);
#pragma unroll
                for (int nt = 0; nt < 4; nt++) {
                    mma_tf32(d[par][mt][nt], ah, bh[nt]);
                    mma_tf32(d[par][mt][nt], al, bh[nt]);
                    mma_tf32(d[par][mt][nt], ah, bl[nt]);
                }
            }
        }
    }

    __syncthreads();
    unsigned* sDh = (unsigned*)wsm;          // [128][68]
    unsigned* sDl = sDh + 128*68;
    const float* kbE = kb + srcrowE;
    const float* kbO = kbE + 768;
#pragma unroll
    for (int mt = 0; mt < 2; mt++) {
        int olo = obase + mt*16 + lr;
        float beL = kbE[(size_t)olo*3],     boL = kbO[(size_t)olo*3];
        float beH = kbE[(size_t)(olo+8)*3], boH = kbO[(size_t)(olo+8)*3];
#pragma unroll
        for (int nt = 0; nt < 4; nt++) {
#pragma unroll
            for (int q = 0; q < 4; q++) {
                int col = cbase + nt*8 + 2*lc + (q & 1);
                int oE  = (q < 2) ? olo : olo + 8;
                float ve = d[0][mt][nt][q] + ((q < 2) ? beL : beH);
                float vo = d[1][mt][nt][q] + ((q < 2) ? boL : boH);
                unsigned he, le, ho, lo2;
                split_bf(ve, he, le);
                split_bf(vo, ho, lo2);
                sDh[col*68 + oE] = he | (ho << 16);
                sDl[col*68 + oE] = le | (lo2 << 16);
            }
        }
    }
    __syncthreads();
    const size_t jrowp = (size_t)(tap*64 + ip)*WROW + o0;   // padded layout
    uint4* gH4 = (uint4*)gWh;
    uint4* gL4 = (uint4*)gWl;
    for (int p = tid; p < 128*16; p += 256) {
        int col = p >> 4, o4 = p & 15;
        size_t adr4 = ((size_t)(nl*128 + col)*SLICE_U32 + jrowp)/4 + o4;
        gH4[adr4] = *(uint4*)(sDh + col*68 + o4*4);
        gL4[adr4] = *(uint4*)(sDl + col*68 + o4*4);
    }
}

// =====================================================================
// 4) LVC layer: bf16 3-term mma, bulk-TMA 4-buffer pipeline
// =====================================================================
#define XSTR 168
#define LVC_XPL (64*XSTR)
#define LVC_WPL (16*WROW)
#define CHUNK_BYTES (LVC_WPL*4)          // 16896
#define LVC_SMEM ((2*LVC_XPL + 8*LVC_WPL + 256)*4)   // 222208 B

template<int D>
__global__ void __launch_bounds__(512, 1)
lvc_kernel(const unsigned* __restrict__ inh, const unsigned* __restrict__ inl,
           float* __restrict__ xout,
           unsigned* __restrict__ outh, unsigned* __restrict__ outl,
           const unsigned* __restrict__ gWh, const unsigned* __restrict__ gWl,
           const float* __restrict__ gbias,
           int n, int layer, int accflag)
{
    extern __shared__ unsigned smu[];
    __shared__ unsigned long long s_mbar[4];
    unsigned* xph = smu;
    unsigned* xpl = smu + LVC_XPL;
    unsigned* wbase_ = smu + 2*LVC_XPL;
    float* sbias  = (float*)(wbase_ + 8*LVC_WPL);

    const int hf  = blockIdx.x;
    const int l   = blockIdx.y;
    const int b   = blockIdx.z;
    const int tid = threadIdx.x;
    const int wid = tid >> 5;
    const int lane = tid & 31;
    const int og = wid >> 2;
    const int obase = og * 64;
    const int sbase = (wid & 3) * 32;
    const int lr = lane >> 2;
    const int lc = lane & 3;

    const int t_base = l*HOPn + hf*128;
    const int win = 128 + 2*D;

    const size_t slice = (size_t)((n*5 + layer)*128 + b*64 + l)*SLICE_U32;
    const char* srcH = (const char*)(gWh + slice);
    const char* srcL = (const char*)(gWl + slice);
    const unsigned mbar0 = (unsigned)__cvta_generic_to_shared(s_mbar);
    const unsigned wsm0  = (unsigned)__cvta_generic_to_shared(wbase_);

    if (tid == 0) {
#pragma unroll
        for (int i = 0; i < 4; i++) mbar_init(mbar0 + i*8, 1);
    }

    for (int p = tid; p < 64*win; p += 512) {
        int jg = p / win;
        int j  = p - jg*win;
        int t  = t_base - D + j;
        unsigned vh = 0, vl = 0;
        if (t >= 0 && t < Tn) {
            size_t idx = ((size_t)(b*64 + jg))*Tn + t;
            vh = inh[idx]; vl = inl[idx];
        }
        xph[jg*XSTR + j] = vh;
        xpl[jg*XSTR + j] = vl;
    }
    if (tid < 256)
        sbias[tid] = gbias[(size_t)(((n*2 + b)*BCHn) + layer*COUTC + tid)*Ln + l];
    __syncthreads();

    if (tid == 0) {
#pragma unroll
        for (int cc = 0; cc < 3; cc++) {
            unsigned mb = mbar0 + (cc & 3)*8;
            unsigned dst = wsm0 + (cc & 3)*2*CHUNK_BYTES;
            mbar_expect(mb, 2*CHUNK_BYTES);
            bulk_ld(dst,               srcH + (size_t)cc*CHUNK_BYTES, CHUNK_BYTES, mb);
            bulk_ld(dst + CHUNK_BYTES, srcL + (size_t)cc*CHUNK_BYTES, CHUNK_BYTES, mb);
        }
    }

    float d[4][4][4];
#pragma unroll
    for (int mt = 0; mt < 4; mt++) {
        int olo = obase + mt*16 + lr;
        float blo = sbias[olo], bhi = sbias[olo + 8];
#pragma unroll
        for (int nt = 0; nt < 4; nt++) {
            d[mt][nt][0] = blo; d[mt][nt][1] = blo;
            d[mt][nt][2] = bhi; d[mt][nt][3] = bhi;
        }
    }

#pragma unroll
    for (int c = 0; c < 12; c++) {
        mbar_wait(mbar0 + (c & 3)*8, (c >> 2) & 1);

        const unsigned* bh_ = wbase_ + (c & 3)*2*LVC_WPL;
        const unsigned* bl_ = bh_ + LVC_WPL;
        const int tap  = c >> 2;
        const int toff = tap * D;
        const int jrow0 = (c & 3) * 16;

#pragma unroll
        for (int ks = 0; ks < 2; ks++) {
            unsigned bh[4][2], bl[4][2];
            const unsigned* bpH = xph + (jrow0 + ks*8 + lc)*XSTR + toff + sbase + lr;
            const unsigned* bpL = xpl + (jrow0 + ks*8 + lc)*XSTR + toff + sbase + lr;
#pragma unroll
            for (int nt = 0; nt < 4; nt++) {
                bh[nt][0] = bpH[nt*8];
                bh[nt][1] = bpH[4*XSTR + nt*8];
                bl[nt][0] = bpL[nt*8];
                bl[nt][1] = bpL[4*XSTR + nt*8];
            }
#pragma unroll
            for (int mt = 0; mt < 4; mt++) {
                const int ap = (ks*8 + lc)*WROW + obase + mt*16 + lr;
                unsigned ah[4], al[4];
                ah[0] = bh_[ap];            ah[1] = bh_[ap + 8];
                ah[2] = bh_[ap + 4*WROW];   ah[3] = bh_[ap + 4*WROW + 8];
                al[0] = bl_[ap];            al[1] = bl_[ap + 8];
                al[2] = bl_[ap + 4*WROW];   al[3] = bl_[ap + 4*WROW + 8];
#pragma unroll
                for (int nt = 0; nt < 4; nt++) {
                    mma_bf16(d[mt][nt], ah, bh[nt]);
                    mma_bf16(d[mt][nt], al, bh[nt]);
                    mma_bf16(d[mt][nt], ah, bl[nt]);
                }
            }
        }

        __syncthreads();
        if (c < 9 && tid == 0) {
            int cc = c + 3;
            unsigned mb = mbar0 + (cc & 3)*8;
            unsigned dst = wsm0 + (cc & 3)*2*CHUNK_BYTES;
            mbar_expect(mb, 2*CHUNK_BYTES);
            bulk_ld(dst,               srcH + (size_t)cc*CHUNK_BYTES, CHUNK_BYTES, mb);
            bulk_ld(dst + CHUNK_BYTES, srcL + (size_t)cc*CHUNK_BYTES, CHUNK_BYTES, mb);
        }
    }
    __syncthreads();

    float* ys2 = (float*)smu;                 // [128][133]
    float* ys3 = (float*)(smu + 2*LVC_XPL);   // [128][132]

    if (og >= 2) {
#pragma unroll
        for (int mt = 0; mt < 4; mt++) {
            int ro = (og - 2)*64 + mt*16 + lr;
#pragma unroll
            for (int nt = 0; nt < 4; nt++) {
                int s = sbase + nt*8 + 2*lc;
                ys2[ro*133 + s]       = d[mt][nt][0];
                ys2[ro*133 + s + 1]   = d[mt][nt][1];
                ys2[(ro+8)*133 + s]   = d[mt][nt][2];
                ys2[(ro+8)*133 + s+1] = d[mt][nt][3];
            }
        }
    }
    __syncthreads();
    if (og < 2) {
#pragma unroll
        for (int mt = 0; mt < 4; mt++) {
#pragma unroll
            for (int q2 = 0; q2 < 2; q2++) {
                int o = obase + mt*16 + lr + q2*8;
#pragma unroll
                for (int nt = 0; nt < 4; nt++) {
#pragma unroll
                    for (int qp = 0; qp < 2; qp++) {
                        int s = sbase + nt*8 + 2*lc + qp;
                        float lov = d[mt][nt][q2*2 + qp];
                        float hiv = ys2[o*133 + s];
                        ys3[o*132 + s] = tanhf(hiv) / (1.f + __expf(-lov));
                    }
                }
            }
        }
    }
    __syncthreads();

    for (int idx = tid; idx < 128*32; idx += 512) {
        int o = idx >> 5, s4 = (idx & 31)*4;
        float4 v = *(float4*)(ys3 + o*132 + s4);
        float4* dp = (float4*)(xout + ((size_t)(b*INNERC + o))*Tn + t_base + s4);
        if (accflag) {
            float4 old = *dp;
            v.x += old.x; v.y += old.y; v.z += old.z; v.w += old.w;
            *(float4*)(ys3 + o*132 + s4) = v;
        }
        *dp = v;
    }
    if (accflag) __syncthreads();
    for (int idx = tid; idx < 64*128; idx += 512) {
        int jg = idx >> 7, s = idx & 127;
        unsigned h0,l0,h1,l1;
        split_bf(ys3[(2*jg)*132 + s],   h0, l0);
        split_bf(ys3[(2*jg+1)*132 + s], h1, l1);
        size_t gidx = ((size_t)(b*64 + jg))*Tn + t_base + s;
        outh[gidx] = h0 | (h1 << 16);
        outl[gidx] = l0 | (l1 << 16);
    }
}

// =====================================================================
// 5) final
// =====================================================================
__global__ void __launch_bounds__(128)
final_kernel(const float* __restrict__ h,
             const float* __restrict__ W1, const float* __restrict__ b1,
             const float* __restrict__ W2, const float* __restrict__ b2,
             float* __restrict__ out)
{
    __shared__ float bufA[64*129];
    __shared__ float bufB[64*32];
    const int b  = blockIdx.y;
    const int t0 = blockIdx.x * 32;
    const int tid = threadIdx.x;

    float acc[32];
    float bv = b1[tid];
#pragma unroll
    for (int j = 0; j < 32; j++) acc[j] = bv;

    for (int c0 = 0; c0 < 128; c0 += 64) {
        __syncthreads();
        for (int p = tid; p < 128*64; p += 128) {
            int o = p >> 6, cl = p & 63;
            bufA[cl*129 + o] = W1[o*128 + c0 + cl];
        }
        for (int p = tid; p < 64*32; p += 128) {
            int cl = p >> 5, j = p & 31;
            float v = h[((size_t)(b*INNERC + c0 + cl))*Tn + t0 + j];
            bufB[p] = v > 0.f ? v : 0.f;
        }
        __syncthreads();
        for (int cl = 0; cl < 64; cl++) {
            float w = bufA[cl*129 + tid];
            const float* xr = &bufB[cl*32];
#pragma unroll
            for (int j = 0; j < 32; j++) acc[j] += w * xr[j];
        }
    }
    __syncthreads();
#pragma unroll
    for (int j = 0; j < 32; j++) bufA[tid*33 + j] = acc[j] > 0.f ? acc[j] : 0.f;
    __syncthreads();
    if (tid < 32) {
        float s = b2[0];
        for (int o = 0; o < 128; o++) s += W2[o] * bufA[o*33 + tid];
        out[(size_t)b*Tn + t0 + tid] = s;
    }
}

// =====================================================================
// launcher — serial producer/consumer interleave for L2 residency:
// slab k immediately before lvc layer k, single stream.
// =====================================================================
extern "C" void kernel_launch(void* const* d_in, const int* in_sizes, int n_in,
                              void* d_out, int out_size)
{
    (void)in_sizes; (void)n_in; (void)out_size;
    const float* x      = (const float*)d_in[0];
    const float* cnd    = (const float*)d_in[1];
    const float* fc_W   = (const float*)d_in[2];
    const float* fc_b   = (const float*)d_in[3];
    const float* inp_W  = (const float*)d_in[4];
    const float* inp_b  = (const float*)d_in[5];
    const float* res1_W = (const float*)d_in[6];
    const float* res1_b = (const float*)d_in[7];
    const float* res2_W = (const float*)d_in[8];
    const float* res2_b = (const float*)d_in[9];
    const float* kern_W = (const float*)d_in[10];
    const float* kern_b = (const float*)d_in[11];
    const float* bc_W   = (const float*)d_in[12];
    const float* bc_b   = (const float*)d_in[13];
    const float* lc1_W  = (const float*)d_in[14];
    const float* lc1_b  = (const float*)d_in[15];
    const float* lc2_W  = (const float*)d_in[16];
    const float* lc2_b  = (const float*)d_in[17];
    float* out = (float*)d_out;

    float *h, *xb, *yb, *hc, *bs, *Bth, *Btl;
    unsigned *hph,*hpl,*xph,*xpl,*yph,*ypl,*Wh,*Wl;
    cudaGetSymbolAddress((void**)&h,  g_h);
    cudaGetSymbolAddress((void**)&xb, g_x1);
    cudaGetSymbolAddress((void**)&yb, g_y1);
    cudaGetSymbolAddress((void**)&hc, g_hc);
    cudaGetSymbolAddress((void**)&bs, g_bs);
    cudaGetSymbolAddress((void**)&Bth, g_Bth);
    cudaGetSymbolAddress((void**)&Btl, g_Btl);
    cudaGetSymbolAddress((void**)&hph, g_hph);
    cudaGetSymbolAddress((void**)&hpl, g_hpl);
    cudaGetSymbolAddress((void**)&xph, g_xph);
    cudaGetSymbolAddress((void**)&xpl, g_xpl);
    cudaGetSymbolAddress((void**)&yph, g_yph);
    cudaGetSymbolAddress((void**)&ypl, g_ypl);
    cudaGetSymbolAddress((void**)&Wh, g_Wh);
    cudaGetSymbolAddress((void**)&Wl, g_Wl);

    static bool s_attr = false;
    if (!s_attr) {
        cudaFuncSetAttribute(wgemm_kernel,   cudaFuncAttributeMaxDynamicSharedMemorySize, WG_SMEM);
        cudaFuncSetAttribute(lvc_kernel<1>,  cudaFuncAttributeMaxDynamicSharedMemorySize, LVC_SMEM);
        cudaFuncSetAttribute(lvc_kernel<2>,  cudaFuncAttributeMaxDynamicSharedMemorySize, LVC_SMEM);
        cudaFuncSetAttribute(lvc_kernel<4>,  cudaFuncAttributeMaxDynamicSharedMemorySize, LVC_SMEM);
        cudaFuncSetAttribute(lvc_kernel<8>,  cudaFuncAttributeMaxDynamicSharedMemorySize, LVC_SMEM);
        cudaFuncSetAttribute(lvc_kernel<16>, cudaFuncAttributeMaxDynamicSharedMemorySize, LVC_SMEM);
        s_attr = true;
    }

    predictor_kernel<<<4, 256>>>(cnd, inp_W, inp_b, res1_W, res1_b,
                                 res2_W, res2_b, bc_W, bc_b, hc, bs, Bth, Btl);
    fc_kernel<<<dim3(Tn/32, Bn), 128>>>(x, fc_W, fc_b, h, hph, hpl);

    for (int n = 0; n < 2; n++) {
        const unsigned *cih = hph, *cil = hpl;
        for (int i = 0; i < 5; i++) {
            // produce slab (n,i) right before its consumer so its 52 MB
            // output is L2-resident when the lvc layer reads it
            wgemm_kernel<<<768, 256, WG_SMEM>>>(kern_W, kern_b, Bth, Btl, Wh, Wl, n*5 + i);

            float* outf; unsigned *oh, *ol;
            if (i == 4)      { outf = h;  oh = hph; ol = hpl; }
            else if (i & 1)  { outf = yb; oh = yph; ol = ypl; }
            else             { outf = xb; oh = xph; ol = xpl; }
            int accfl = (i == 4 && n == 1) ? 1 : 0;
            dim3 g(2, Ln, Bn);
            switch (i) {
                case 0: lvc_kernel<1> <<<g, 512, LVC_SMEM>>>(cih, cil, outf, oh, ol, Wh, Wl, bs, n, i, accfl); break;
                case 1: lvc_kernel<2> <<<g, 512, LVC_SMEM>>>(cih, cil, outf, oh, ol, Wh, Wl, bs, n, i, accfl); break;
                case 2: lvc_kernel<4> <<<g, 512, LVC_SMEM>>>(cih, cil, outf, oh, ol, Wh, Wl, bs, n, i, accfl); break;
                case 3: lvc_kernel<8> <<<g, 512, LVC_SMEM>>>(cih, cil, outf, oh, ol, Wh, Wl, bs, n, i, accfl); break;
                case 4: lvc_kernel<16><<<g, 512, LVC_SMEM>>>(cih, cil, outf, oh, ol, Wh, Wl, bs, n, i, accfl); break;
            }
            cih = oh; cil = ol;
        }
    }

    final_kernel<<<dim3(Tn/32, Bn), 128>>>(h, lc1_W, lc1_b, lc2_W, lc2_b, out);
}

// round 13
// speedup vs baseline: 1.0815x; 1.0815x over previous
#include <cuda_runtime.h>
#include <cuda_bf16.h>
#include <math.h>

// ---------------- problem constants ----------------
#define Bn      2
#define Tn      16384
#define Ln      64
#define HOPn    256
#define INCH    101
#define INNERC  128
#define CONDC   81
#define KHC     64
#define COUTC   256
#define KCHn    491520          // 5*128*256*3
#define BCHn    1280            // 256*5
#define WROW    264
#define SLICE_U32 50688         // 192*264 u32 per plane per slice

// ---------------- numeric helpers ----------------
__device__ __forceinline__ unsigned f2tf(float f) {
    unsigned u; asm("cvt.rna.tf32.f32 %0, %1;" : "=r"(u) : "f"(f)); return u;
}
__device__ __forceinline__ void split_tf(float v, float& hi, float& lo) {
    hi = __uint_as_float(f2tf(v));
    lo = __uint_as_float(f2tf(v - hi));
}
__device__ __forceinline__ void split_bf(float v, unsigned& h, unsigned& l) {
    __nv_bfloat16 hb = __float2bfloat16_rn(v);
    float hf = __bfloat162float(hb);
    __nv_bfloat16 lb = __float2bfloat16_rn(v - hf);
    h = (unsigned)__bfloat16_as_ushort(hb);
    l = (unsigned)__bfloat16_as_ushort(lb);
}
__device__ __forceinline__ void mma_tf32(float* d, const unsigned* a, const unsigned* b) {
    asm("mma.sync.aligned.m16n8k8.row.col.f32.tf32.tf32.f32 "
        "{%0,%1,%2,%3}, {%4,%5,%6,%7}, {%8,%9}, {%0,%1,%2,%3};"
        : "+f"(d[0]), "+f"(d[1]), "+f"(d[2]), "+f"(d[3])
        : "r"(a[0]), "r"(a[1]), "r"(a[2]), "r"(a[3]), "r"(b[0]), "r"(b[1]));
}
__device__ __forceinline__ void mma_bf16(float* d, const unsigned* a, const unsigned* b) {
    asm("mma.sync.aligned.m16n8k16.row.col.f32.bf16.bf16.f32 "
        "{%0,%1,%2,%3}, {%4,%5,%6,%7}, {%8,%9}, {%0,%1,%2,%3};"
        : "+f"(d[0]), "+f"(d[1]), "+f"(d[2]), "+f"(d[3])
        : "r"(a[0]), "r"(a[1]), "r"(a[2]), "r"(a[3]), "r"(b[0]), "r"(b[1]));
}
// bulk-TMA multicast load + mbarrier
__device__ __forceinline__ void bulk_ld_mc(unsigned dst_smem, const void* gsrc,
                                           unsigned bytes, unsigned mbar,
                                           unsigned short mask) {
    asm volatile("cp.async.bulk.shared::cluster.global.mbarrier::complete_tx::bytes"
                 ".multicast::cluster [%0], [%1], %2, [%3], %4;"
                 :: "r"(dst_smem), "l"(gsrc), "r"(bytes), "r"(mbar), "h"(mask) : "memory");
}
__device__ __forceinline__ void mbar_init(unsigned mbar, unsigned cnt) {
    asm volatile("mbarrier.init.shared.b64 [%0], %1;" :: "r"(mbar), "r"(cnt) : "memory");
}
__device__ __forceinline__ void mbar_expect(unsigned mbar, unsigned bytes) {
    asm volatile("mbarrier.arrive.expect_tx.shared.b64 _, [%0], %1;"
                 :: "r"(mbar), "r"(bytes) : "memory");
}
__device__ __forceinline__ void mbar_wait(unsigned mbar, unsigned parity) {
    asm volatile(
        "{\n\t.reg .pred P1;\n\t"
        "WAIT_LOOP_%=:\n\t"
        "mbarrier.try_wait.parity.acquire.cta.shared::cta.b64 P1, [%0], %1, 0x989680;\n\t"
        "@P1 bra.uni WAIT_DONE_%=;\n\t"
        "bra.uni WAIT_LOOP_%=;\n\t"
        "WAIT_DONE_%=:\n\t}"
        :: "r"(mbar), "r"(parity) : "memory");
}
__device__ __forceinline__ void cluster_sync_all() {
    asm volatile("barrier.cluster.arrive.aligned;" ::: "memory");
    asm volatile("barrier.cluster.wait.aligned;"   ::: "memory");
}

// ---------------- scratch ----------------
__device__ float    g_h [Bn*INNERC*Tn];
__device__ float    g_x1[Bn*INNERC*Tn];
__device__ float    g_y1[Bn*INNERC*Tn];
__device__ unsigned g_hph[Bn*64*Tn], g_hpl[Bn*64*Tn];
__device__ unsigned g_xph[Bn*64*Tn], g_xpl[Bn*64*Tn];
__device__ unsigned g_yph[Bn*64*Tn], g_ypl[Bn*64*Tn];
__device__ float    g_hc[2*Bn*KHC*Ln];
__device__ float    g_bs[2*Bn*BCHn*Ln];
__device__ float    g_Bth[2*64*128], g_Btl[2*64*128];
__device__ unsigned g_Wh[(size_t)1280*SLICE_U32];
__device__ unsigned g_Wl[(size_t)1280*SLICE_U32];

// =====================================================================
// 1) fc
// =====================================================================
__global__ void __launch_bounds__(128)
fc_kernel(const float* __restrict__ x,
          const float* __restrict__ W,
          const float* __restrict__ bias,
          float* __restrict__ out,
          unsigned* __restrict__ outh,
          unsigned* __restrict__ outl)
{
    __shared__ float sx[INCH*32];
    __shared__ float sW[128*33];
    const int b  = blockIdx.y;
    const int t0 = blockIdx.x * 32;
    const int tid = threadIdx.x;

    for (int p = tid; p < INCH*32; p += 128) {
        int c = p >> 5, j = p & 31;
        sx[p] = x[((size_t)(b*INCH + c))*Tn + t0 + j];
    }
    float acc[32];
    float bv = bias[tid];
#pragma unroll
    for (int j = 0; j < 32; j++) acc[j] = bv;

    for (int c0 = 0; c0 < INCH; c0 += 32) {
        int cmax = (INCH - c0) < 32 ? (INCH - c0) : 32;
        __syncthreads();
        for (int p = tid; p < 128*32; p += 128) {
            int o = p >> 5, cl = p & 31;
            if (cl < cmax) sW[o*33 + cl] = W[o*INCH + c0 + cl];
        }
        __syncthreads();
        for (int cl = 0; cl < cmax; cl++) {
            float w = sW[tid*33 + cl];
            const float* xr = &sx[(c0 + cl)*32];
#pragma unroll
            for (int j = 0; j < 32; j++) acc[j] += w * xr[j];
        }
    }
    float* o = &out[((size_t)(b*INNERC + tid))*Tn + t0];
#pragma unroll
    for (int j = 0; j < 32; j++) o[j] = acc[j];

    __syncthreads();
#pragma unroll
    for (int j = 0; j < 32; j++) sW[tid*33 + j] = acc[j];
    __syncthreads();
    for (int p = tid; p < 64*32; p += 128) {
        int jg = p >> 5, t = p & 31;
        unsigned h0,l0,h1,l1;
        split_bf(sW[(2*jg)*33 + t],   h0, l0);
        split_bf(sW[(2*jg+1)*33 + t], h1, l1);
        size_t idx = ((size_t)(b*64 + jg))*Tn + t0 + t;
        outh[idx] = h0 | (h1 << 16);
        outl[idx] = l0 | (l1 << 16);
    }
}

// =====================================================================
// 2) kernel predictor
// =====================================================================
__global__ void __launch_bounds__(256)
predictor_kernel(const float* __restrict__ cond,
                 const float* __restrict__ iW, const float* __restrict__ ib,
                 const float* __restrict__ r1W, const float* __restrict__ r1b,
                 const float* __restrict__ r2W, const float* __restrict__ r2b,
                 const float* __restrict__ bW,  const float* __restrict__ bb,
                 float* __restrict__ hc_out, float* __restrict__ bias_out,
                 float* __restrict__ Bth, float* __restrict__ Btl)
{
    __shared__ float bufc[CONDC*Ln];
    __shared__ float bufh[KHC*Ln];
    const int nb = blockIdx.x;
    const int n  = nb >> 1;
    const int b  = nb & 1;
    const int tid = threadIdx.x;
    const int NT = 256;

    for (int p = tid; p < CONDC*Ln; p += NT) bufc[p] = cond[b*CONDC*Ln + p];
    __syncthreads();

    for (int idx = tid; idx < KHC*Ln; idx += NT) {
        int kh = idx >> 6, l = idx & 63;
        float a = ib[n*KHC + kh];
        const float* wrow = &iW[(size_t)(n*KHC + kh)*CONDC*5];
        for (int cc = 0; cc < CONDC; cc++) {
#pragma unroll
            for (int k = 0; k < 5; k++) {
                int ll = l + k - 2;
                if (ll >= 0 && ll < Ln) a += bufc[cc*Ln + ll] * wrow[cc*5 + k];
            }
        }
        bufh[idx] = a >= 0.f ? a : 0.1f*a;
    }
    __syncthreads();

    for (int idx = tid; idx < KHC*Ln; idx += NT) {
        int o = idx >> 6, l = idx & 63;
        float a = r1b[n*KHC + o];
        const float* wr = &r1W[(size_t)(n*KHC + o)*KHC];
        for (int i = 0; i < KHC; i++) a += wr[i] * bufh[i*Ln + l];
        bufc[idx] = a >= 0.f ? a : 0.1f*a;
    }
    __syncthreads();

    for (int idx = tid; idx < KHC*Ln; idx += NT) {
        int o = idx >> 6, l = idx & 63;
        float a = r2b[n*KHC + o];
        const float* wr = &r2W[(size_t)(n*KHC + o)*KHC];
        for (int i = 0; i < KHC; i++) a += wr[i] * bufc[i*Ln + l];
        bufh[idx] = bufh[idx] + a;
    }
    __syncthreads();

    for (int idx = tid; idx < KHC*Ln; idx += NT) hc_out[nb*KHC*Ln + idx] = bufh[idx];

    for (int idx = tid; idx < KHC*Ln; idx += NT) {
        int k = idx >> 6, l = idx & 63;
        float h, lo; split_tf(bufh[k*Ln + l], h, lo);
        int col = b*64 + l;
        Bth[(n*64 + k)*128 + col] = h;
        Btl[(n*64 + k)*128 + col] = lo;
    }

    for (int idx = tid; idx < BCHn*Ln; idx += NT) {
        int j = idx >> 6, l = idx & 63;
        float a = bb[n*BCHn + j];
        const float* wr = &bW[(size_t)(n*BCHn + j)*KHC];
        for (int i = 0; i < KHC; i++) a += wr[i] * bufh[i*Ln + l];
        bias_out[(size_t)nb*BCHn*Ln + idx] = a;
    }
}

// =====================================================================
// 3) weight GEMM per slab nl (side stream)
// =====================================================================
#define WG_SA 4352
#define WG_SB 8704
#define WG_SMEM ((2*WG_SA + 2*WG_SB) * (int)sizeof(float))

__global__ void __launch_bounds__(256)
wgemm_kernel(const float* __restrict__ kW,
             const float* __restrict__ kb,
             const float* __restrict__ Bth,
             const float* __restrict__ Btl,
             unsigned* __restrict__ gWh,
             unsigned* __restrict__ gWl,
             int nl)
{
    extern __shared__ float wsm[];
    float* sAh = wsm;
    float* sAl = wsm + WG_SA;
    float* sBh = wsm + 2*WG_SA;
    float* sBl = wsm + 2*WG_SA + WG_SB;

    const int tid  = threadIdx.x;
    const int bx   = blockIdx.x;
    const int n    = nl / 5, layer = nl % 5;
    const int ip   = bx / 12;
    const int rem  = bx % 12;
    const int tap  = rem >> 2;
    const int o0   = (rem & 3) * 64;

    const size_t nbase = (size_t)n*KCHn + (size_t)layer*(384*256);
    const size_t srcrowE = nbase + (size_t)(2*ip)*768 + (size_t)o0*3 + tap;

    {
        const float4* srcH4 = (const float4*)(Bth + n*8192);
        const float4* srcL4 = (const float4*)(Btl + n*8192);
        for (int p4 = tid; p4 < 64*32; p4 += 256) {
            int k = p4 >> 5, c4 = p4 & 31;
            *(float4*)(sBh + k*136 + c4*4) = srcH4[p4];
            *(float4*)(sBl + k*136 + c4*4) = srcL4[p4];
        }
    }

    const int wid  = tid >> 5;
    const int lane = tid & 31;
    const int obase = (wid >> 2) * 32;
    const int cbase = (wid & 3) * 32;
    const int lr = lane >> 2;
    const int lc = lane & 3;

    float d[2][2][4][4];
#pragma unroll
    for (int p = 0; p < 2; p++)
#pragma unroll
        for (int mt = 0; mt < 2; mt++)
#pragma unroll
            for (int nt = 0; nt < 4; nt++)
#pragma unroll
                for (int q = 0; q < 4; q++) d[p][mt][nt][q] = 0.f;

    const float4* kW4 = (const float4*)kW;
#pragma unroll
    for (int par = 0; par < 2; par++) {
        __syncthreads();
        const size_t srcrow = srcrowE + (size_t)par*768;
        for (int p4 = tid; p4 < 64*16; p4 += 256) {
            int r = p4 >> 4, kq = p4 & 15;
            float4 v = kW4[srcrow*16 + (size_t)r*48 + kq];
            float h0,l0,h1,l1,h2,l2,h3,l3;
            split_tf(v.x,h0,l0); split_tf(v.y,h1,l1);
            split_tf(v.z,h2,l2); split_tf(v.w,h3,l3);
            float* dh = sAh + r*68 + kq*4;
            float* dl = sAl + r*68 + kq*4;
            dh[0]=h0; dh[1]=h1; dh[2]=h2; dh[3]=h3;
            dl[0]=l0; dl[1]=l1; dl[2]=l2; dl[3]=l3;
        }
        __syncthreads();

#pragma unroll
        for (int ks = 0; ks < 8; ks++) {
            unsigned bh[4][2], bl[4][2];
            const float* bpH = sBh + (ks*8 + lc)*136 + cbase + lr;
            const float* bpL = sBl + (ks*8 + lc)*136 + cbase + lr;
#pragma unroll
            for (int nt = 0; nt < 4; nt++) {
                bh[nt][0] = __float_as_uint(bpH[nt*8]);
                bh[nt][1] = __float_as_uint(bpH[4*136 + nt*8]);
                bl[nt][0] = __float_as_uint(bpL[nt*8]);
                bl[nt][1] = __float_as_uint(bpL[4*136 + nt*8]);
            }
#pragma unroll
            for (int mt = 0; mt < 2; mt++) {
                const int ap = (obase + mt*16 + lr)*68 + ks*8 + lc;
                unsigned ah[4], al[4];
                ah[0] = __float_as_uint(sAh[ap]);
                ah[1] = __float_as_uint(sAh[ap + 8*68]);
                ah[2] = __float_as_uint(sAh[ap + 4]);
                ah[3] = __float_as_uint(sAh[ap + 8*68 + 4]);
                al[0] = __float_as_uint(sAl[ap]);
                al[1] = __float_as_uint(sAl[ap + 8*68]);
                al[2] = __float_as_uint(sAl[ap + 4]);
                al[3] = __float_as_uint(sAl[ap + 8*68 + 4]);
#pragma unroll
                for (int nt = 0; nt < 4; nt++) {
                    mma_tf32(d[par][mt][nt], ah, bh[nt]);
                    mma_tf32(d[par][mt][nt], al, bh[nt]);
                    mma_tf32(d[par][mt][nt], ah, bl[nt]);
                }
            }
        }
    }

    __syncthreads();
    unsigned* sDh = (unsigned*)wsm;
    unsigned* sDl = sDh + 128*68;
    const float* kbE = kb + srcrowE;
    const float* kbO = kbE + 768;
#pragma unroll
    for (int mt = 0; mt < 2; mt++) {
        int olo = obase + mt*16 + lr;
        float beL = kbE[(size_t)olo*3],     boL = kbO[(size_t)olo*3];
        float beH = kbE[(size_t)(olo+8)*3], boH = kbO[(size_t)(olo+8)*3];
#pragma unroll
        for (int nt = 0; nt < 4; nt++) {
#pragma unroll
            for (int q = 0; q < 4; q++) {
                int col = cbase + nt*8 + 2*lc + (q & 1);
                int oE  = (q < 2) ? olo : olo + 8;
                float ve = d[0][mt][nt][q] + ((q < 2) ? beL : beH);
                float vo = d[1][mt][nt][q] + ((q < 2) ? boL : boH);
                unsigned he, le, ho, lo2;
                split_bf(ve, he, le);
                split_bf(vo, ho, lo2);
                sDh[col*68 + oE] = he | (ho << 16);
                sDl[col*68 + oE] = le | (lo2 << 16);
            }
        }
    }
    __syncthreads();
    const size_t jrowp = (size_t)(tap*64 + ip)*WROW + o0;
    uint4* gH4 = (uint4*)gWh;
    uint4* gL4 = (uint4*)gWl;
    for (int p = tid; p < 128*16; p += 256) {
        int col = p >> 4, o4 = p & 15;
        size_t adr4 = ((size_t)(nl*128 + col)*SLICE_U32 + jrowp)/4 + o4;
        gH4[adr4] = *(uint4*)(sDh + col*68 + o4*4);
        gL4[adr4] = *(uint4*)(sDl + col*68 + o4*4);
    }
}

// =====================================================================
// 4) LVC layer: bf16 3-term mma, cluster(2) TMA multicast pipeline.
//    Cluster pairs hf=0/1 which share the same weight slice (b,l).
// =====================================================================
#define XSTR 168
#define LVC_XPL (64*XSTR)
#define LVC_WPL (16*WROW)
#define CHUNK_BYTES (LVC_WPL*4)          // 16896
#define LVC_SMEM ((2*LVC_XPL + 8*LVC_WPL + 256)*4)   // 222208 B

template<int D>
__global__ void __launch_bounds__(512, 1) __cluster_dims__(2, 1, 1)
lvc_kernel(const unsigned* __restrict__ inh, const unsigned* __restrict__ inl,
           float* __restrict__ xout,
           unsigned* __restrict__ outh, unsigned* __restrict__ outl,
           const unsigned* __restrict__ gWh, const unsigned* __restrict__ gWl,
           const float* __restrict__ gbias,
           int n, int layer, int accflag)
{
    extern __shared__ unsigned smu[];
    __shared__ unsigned long long s_mbar[4];
    unsigned* xph = smu;
    unsigned* xpl = smu + LVC_XPL;
    unsigned* wbase_ = smu + 2*LVC_XPL;
    float* sbias  = (float*)(wbase_ + 8*LVC_WPL);

    const int hf  = blockIdx.x;          // == cluster rank
    const int l   = blockIdx.y;
    const int b   = blockIdx.z;
    const int tid = threadIdx.x;
    const int wid = tid >> 5;
    const int lane = tid & 31;
    const int og = wid >> 2;
    const int obase = og * 64;
    const int sbase = (wid & 3) * 32;
    const int lr = lane >> 2;
    const int lc = lane & 3;

    const int t_base = l*HOPn + hf*128;
    const int win = 128 + 2*D;

    const size_t slice = (size_t)((n*5 + layer)*128 + b*64 + l)*SLICE_U32;
    const char* srcH = (const char*)(gWh + slice);
    const char* srcL = (const char*)(gWl + slice);
    const unsigned mbar0 = (unsigned)__cvta_generic_to_shared(s_mbar);
    const unsigned wsm0  = (unsigned)__cvta_generic_to_shared(wbase_);
    const unsigned short MCAST = 0x3;

    if (tid == 0) {
#pragma unroll
        for (int i = 0; i < 4; i++) mbar_init(mbar0 + i*8, 1);
    }

    // stage packed x window (zero-padded) — differs per hf
    for (int p = tid; p < 64*win; p += 512) {
        int jg = p / win;
        int j  = p - jg*win;
        int t  = t_base - D + j;
        unsigned vh = 0, vl = 0;
        if (t >= 0 && t < Tn) {
            size_t idx = ((size_t)(b*64 + jg))*Tn + t;
            vh = inh[idx]; vl = inl[idx];
        }
        xph[jg*XSTR + j] = vh;
        xpl[jg*XSTR + j] = vl;
    }
    if (tid < 256)
        sbias[tid] = gbias[(size_t)(((n*2 + b)*BCHn) + layer*COUTC + tid)*Ln + l];
    __syncthreads();

    // expects for buffers 0..2 on BOTH CTAs, then cluster barrier, then
    // rank 0 issues the multicast loads.
    if (tid == 0) {
#pragma unroll
        for (int cc = 0; cc < 3; cc++)
            mbar_expect(mbar0 + cc*8, 2*CHUNK_BYTES);
    }
    cluster_sync_all();
    if (hf == 0 && tid == 0) {
#pragma unroll
        for (int cc = 0; cc < 3; cc++) {
            unsigned mb = mbar0 + cc*8;
            unsigned dst = wsm0 + cc*2*CHUNK_BYTES;
            bulk_ld_mc(dst,               srcH + (size_t)cc*CHUNK_BYTES, CHUNK_BYTES, mb, MCAST);
            bulk_ld_mc(dst + CHUNK_BYTES, srcL + (size_t)cc*CHUNK_BYTES, CHUNK_BYTES, mb, MCAST);
        }
    }

    float d[4][4][4];
#pragma unroll
    for (int mt = 0; mt < 4; mt++) {
        int olo = obase + mt*16 + lr;
        float blo = sbias[olo], bhi = sbias[olo + 8];
#pragma unroll
        for (int nt = 0; nt < 4; nt++) {
            d[mt][nt][0] = blo; d[mt][nt][1] = blo;
            d[mt][nt][2] = bhi; d[mt][nt][3] = bhi;
        }
    }

#pragma unroll
    for (int c = 0; c < 12; c++) {
        mbar_wait(mbar0 + (c & 3)*8, (c >> 2) & 1);

        const unsigned* bh_ = wbase_ + (c & 3)*2*LVC_WPL;
        const unsigned* bl_ = bh_ + LVC_WPL;
        const int tap  = c >> 2;
        const int toff = tap * D;
        const int jrow0 = (c & 3) * 16;

#pragma unroll
        for (int ks = 0; ks < 2; ks++) {
            unsigned bh[4][2], bl[4][2];
            const unsigned* bpH = xph + (jrow0 + ks*8 + lc)*XSTR + toff + sbase + lr;
            const unsigned* bpL = xpl + (jrow0 + ks*8 + lc)*XSTR + toff + sbase + lr;
#pragma unroll
            for (int nt = 0; nt < 4; nt++) {
                bh[nt][0] = bpH[nt*8];
                bh[nt][1] = bpH[4*XSTR + nt*8];
                bl[nt][0] = bpL[nt*8];
                bl[nt][1] = bpL[4*XSTR + nt*8];
            }
#pragma unroll
            for (int mt = 0; mt < 4; mt++) {
                const int ap = (ks*8 + lc)*WROW + obase + mt*16 + lr;
                unsigned ah[4], al[4];
                ah[0] = bh_[ap];            ah[1] = bh_[ap + 8];
                ah[2] = bh_[ap + 4*WROW];   ah[3] = bh_[ap + 4*WROW + 8];
                al[0] = bl_[ap];            al[1] = bl_[ap + 8];
                al[2] = bl_[ap + 4*WROW];   al[3] = bl_[ap + 4*WROW + 8];
#pragma unroll
                for (int nt = 0; nt < 4; nt++) {
                    mma_bf16(d[mt][nt], ah, bh[nt]);
                    mma_bf16(d[mt][nt], al, bh[nt]);
                    mma_bf16(d[mt][nt], ah, bl[nt]);
                }
            }
        }

        __syncthreads();                 // local consumers done with oldest buffer
        if (c < 9 && tid == 0)
            mbar_expect(mbar0 + ((c+3) & 3)*8, 2*CHUNK_BYTES);
        cluster_sync_all();              // peer consumers done + expects posted
        if (c < 9 && hf == 0 && tid == 0) {
            int cc = c + 3;
            unsigned mb = mbar0 + (cc & 3)*8;
            unsigned dst = wsm0 + (cc & 3)*2*CHUNK_BYTES;
            bulk_ld_mc(dst,               srcH + (size_t)cc*CHUNK_BYTES, CHUNK_BYTES, mb, MCAST);
            bulk_ld_mc(dst + CHUNK_BYTES, srcL + (size_t)cc*CHUNK_BYTES, CHUNK_BYTES, mb, MCAST);
        }
    }
    __syncthreads();

    float* ys2 = (float*)smu;                 // [128][133]
    float* ys3 = (float*)(smu + 2*LVC_XPL);   // [128][132]

    if (og >= 2) {
#pragma unroll
        for (int mt = 0; mt < 4; mt++) {
            int ro = (og - 2)*64 + mt*16 + lr;
#pragma unroll
            for (int nt = 0; nt < 4; nt++) {
                int s = sbase + nt*8 + 2*lc;
                ys2[ro*133 + s]       = d[mt][nt][0];
                ys2[ro*133 + s + 1]   = d[mt][nt][1];
                ys2[(ro+8)*133 + s]   = d[mt][nt][2];
                ys2[(ro+8)*133 + s+1] = d[mt][nt][3];
            }
        }
    }
    __syncthreads();
    if (og < 2) {
#pragma unroll
        for (int mt = 0; mt < 4; mt++) {
#pragma unroll
            for (int q2 = 0; q2 < 2; q2++) {
                int o = obase + mt*16 + lr + q2*8;
#pragma unroll
                for (int nt = 0; nt < 4; nt++) {
#pragma unroll
                    for (int qp = 0; qp < 2; qp++) {
                        int s = sbase + nt*8 + 2*lc + qp;
                        float lov = d[mt][nt][q2*2 + qp];
                        float hiv = ys2[o*133 + s];
                        ys3[o*132 + s] = tanhf(hiv) / (1.f + __expf(-lov));
                    }
                }
            }
        }
    }
    __syncthreads();

    for (int idx = tid; idx < 128*32; idx += 512) {
        int o = idx >> 5, s4 = (idx & 31)*4;
        float4 v = *(float4*)(ys3 + o*132 + s4);
        float4* dp = (float4*)(xout + ((size_t)(b*INNERC + o))*Tn + t_base + s4);
        if (accflag) {
            float4 old = *dp;
            v.x += old.x; v.y += old.y; v.z += old.z; v.w += old.w;
            *(float4*)(ys3 + o*132 + s4) = v;
        }
        *dp = v;
    }
    if (accflag) __syncthreads();
    for (int idx = tid; idx < 64*128; idx += 512) {
        int jg = idx >> 7, s = idx & 127;
        unsigned h0,l0,h1,l1;
        split_bf(ys3[(2*jg)*132 + s],   h0, l0);
        split_bf(ys3[(2*jg+1)*132 + s], h1, l1);
        size_t gidx = ((size_t)(b*64 + jg))*Tn + t_base + s;
        outh[gidx] = h0 | (h1 << 16);
        outl[gidx] = l0 | (l1 << 16);
    }
    cluster_sync_all();   // no CTA exits while peer multicasts may target it
}

// =====================================================================
// 5) final
// =====================================================================
__global__ void __launch_bounds__(128)
final_kernel(const float* __restrict__ h,
             const float* __restrict__ W1, const float* __restrict__ b1,
             const float* __restrict__ W2, const float* __restrict__ b2,
             float* __restrict__ out)
{
    __shared__ float bufA[64*129];
    __shared__ float bufB[64*32];
    const int b  = blockIdx.y;
    const int t0 = blockIdx.x * 32;
    const int tid = threadIdx.x;

    float acc[32];
    float bv = b1[tid];
#pragma unroll
    for (int j = 0; j < 32; j++) acc[j] = bv;

    for (int c0 = 0; c0 < 128; c0 += 64) {
        __syncthreads();
        for (int p = tid; p < 128*64; p += 128) {
            int o = p >> 6, cl = p & 63;
            bufA[cl*129 + o] = W1[o*128 + c0 + cl];
        }
        for (int p = tid; p < 64*32; p += 128) {
            int cl = p >> 5, j = p & 31;
            float v = h[((size_t)(b*INNERC + c0 + cl))*Tn + t0 + j];
            bufB[p] = v > 0.f ? v : 0.f;
        }
        __syncthreads();
        for (int cl = 0; cl < 64; cl++) {
            float w = bufA[cl*129 + tid];
            const float* xr = &bufB[cl*32];
#pragma unroll
            for (int j = 0; j < 32; j++) acc[j] += w * xr[j];
        }
    }
    __syncthreads();
#pragma unroll
    for (int j = 0; j < 32; j++) bufA[tid*33 + j] = acc[j] > 0.f ? acc[j] : 0.f;
    __syncthreads();
    if (tid < 32) {
        float s = b2[0];
        for (int o = 0; o < 128; o++) s += W2[o] * bufA[o*33 + tid];
        out[(size_t)b*Tn + t0 + tid] = s;
    }
}

// =====================================================================
// launcher — R11 structure: wgemm slabs on side stream, event-chained
// =====================================================================
extern "C" void kernel_launch(void* const* d_in, const int* in_sizes, int n_in,
                              void* d_out, int out_size)
{
    (void)in_sizes; (void)n_in; (void)out_size;
    const float* x      = (const float*)d_in[0];
    const float* cnd    = (const float*)d_in[1];
    const float* fc_W   = (const float*)d_in[2];
    const float* fc_b   = (const float*)d_in[3];
    const float* inp_W  = (const float*)d_in[4];
    const float* inp_b  = (const float*)d_in[5];
    const float* res1_W = (const float*)d_in[6];
    const float* res1_b = (const float*)d_in[7];
    const float* res2_W = (const float*)d_in[8];
    const float* res2_b = (const float*)d_in[9];
    const float* kern_W = (const float*)d_in[10];
    const float* kern_b = (const float*)d_in[11];
    const float* bc_W   = (const float*)d_in[12];
    const float* bc_b   = (const float*)d_in[13];
    const float* lc1_W  = (const float*)d_in[14];
    const float* lc1_b  = (const float*)d_in[15];
    const float* lc2_W  = (const float*)d_in[16];
    const float* lc2_b  = (const float*)d_in[17];
    float* out = (float*)d_out;

    float *h, *xb, *yb, *hc, *bs, *Bth, *Btl;
    unsigned *hph,*hpl,*xph,*xpl,*yph,*ypl,*Wh,*Wl;
    cudaGetSymbolAddress((void**)&h,  g_h);
    cudaGetSymbolAddress((void**)&xb, g_x1);
    cudaGetSymbolAddress((void**)&yb, g_y1);
    cudaGetSymbolAddress((void**)&hc, g_hc);
    cudaGetSymbolAddress((void**)&bs, g_bs);
    cudaGetSymbolAddress((void**)&Bth, g_Bth);
    cudaGetSymbolAddress((void**)&Btl, g_Btl);
    cudaGetSymbolAddress((void**)&hph, g_hph);
    cudaGetSymbolAddress((void**)&hpl, g_hpl);
    cudaGetSymbolAddress((void**)&xph, g_xph);
    cudaGetSymbolAddress((void**)&xpl, g_xpl);
    cudaGetSymbolAddress((void**)&yph, g_yph);
    cudaGetSymbolAddress((void**)&ypl, g_ypl);
    cudaGetSymbolAddress((void**)&Wh, g_Wh);
    cudaGetSymbolAddress((void**)&Wl, g_Wl);

    static cudaStream_t s_side = nullptr;
    static cudaEvent_t  s_fork = nullptr;
    static cudaEvent_t  s_slab[10];
    static bool s_attr = false;
    if (!s_side) {
        cudaStreamCreateWithFlags(&s_side, cudaStreamNonBlocking);
        cudaEventCreateWithFlags(&s_fork, cudaEventDisableTiming);
        for (int i = 0; i < 10; i++)
            cudaEventCreateWithFlags(&s_slab[i], cudaEventDisableTiming);
    }
    if (!s_attr) {
        cudaFuncSetAttribute(wgemm_kernel,   cudaFuncAttributeMaxDynamicSharedMemorySize, WG_SMEM);
        cudaFuncSetAttribute(lvc_kernel<1>,  cudaFuncAttributeMaxDynamicSharedMemorySize, LVC_SMEM);
        cudaFuncSetAttribute(lvc_kernel<2>,  cudaFuncAttributeMaxDynamicSharedMemorySize, LVC_SMEM);
        cudaFuncSetAttribute(lvc_kernel<4>,  cudaFuncAttributeMaxDynamicSharedMemorySize, LVC_SMEM);
        cudaFuncSetAttribute(lvc_kernel<8>,  cudaFuncAttributeMaxDynamicSharedMemorySize, LVC_SMEM);
        cudaFuncSetAttribute(lvc_kernel<16>, cudaFuncAttributeMaxDynamicSharedMemorySize, LVC_SMEM);
        s_attr = true;
    }

    predictor_kernel<<<4, 256>>>(cnd, inp_W, inp_b, res1_W, res1_b,
                                 res2_W, res2_b, bc_W, bc_b, hc, bs, Bth, Btl);
    cudaEventRecord(s_fork, 0);
    cudaStreamWaitEvent(s_side, s_fork, 0);

    for (int nl = 0; nl < 10; nl++) {
        wgemm_kernel<<<768, 256, WG_SMEM, s_side>>>(kern_W, kern_b, Bth, Btl, Wh, Wl, nl);
        cudaEventRecord(s_slab[nl], s_side);
    }

    fc_kernel<<<dim3(Tn/32, Bn), 128>>>(x, fc_W, fc_b, h, hph, hpl);

    for (int n = 0; n < 2; n++) {
        const unsigned *cih = hph, *cil = hpl;
        for (int i = 0; i < 5; i++) {
            float* outf; unsigned *oh, *ol;
            if (i == 4)      { outf = h;  oh = hph; ol = hpl; }
            else if (i & 1)  { outf = yb; oh = yph; ol = ypl; }
            else             { outf = xb; oh = xph; ol = xpl; }
            int accfl = (i == 4 && n == 1) ? 1 : 0;
            cudaStreamWaitEvent(0, s_slab[n*5 + i], 0);
            dim3 g(2, Ln, Bn);
            switch (i) {
                case 0: lvc_kernel<1> <<<g, 512, LVC_SMEM>>>(cih, cil, outf, oh, ol, Wh, Wl, bs, n, i, accfl); break;
                case 1: lvc_kernel<2> <<<g, 512, LVC_SMEM>>>(cih, cil, outf, oh, ol, Wh, Wl, bs, n, i, accfl); break;
                case 2: lvc_kernel<4> <<<g, 512, LVC_SMEM>>>(cih, cil, outf, oh, ol, Wh, Wl, bs, n, i, accfl); break;
                case 3: lvc_kernel<8> <<<g, 512, LVC_SMEM>>>(cih, cil, outf, oh, ol, Wh, Wl, bs, n, i, accfl); break;
                case 4: lvc_kernel<16><<<g, 512, LVC_SMEM>>>(cih, cil, outf, oh, ol, Wh, Wl, bs, n, i, accfl); break;
            }
            cih = oh; cil = ol;
        }
    }

    final_kernel<<<dim3(Tn/32, Bn), 128>>>(h, lc1_W, lc1_b, lc2_W, lc2_b, out);
}

// round 14
// speedup vs baseline: 1.2093x; 1.1181x over previous
#include <cuda_runtime.h>
#include <cuda_bf16.h>
#include <math.h>

// ---------------- problem constants ----------------
#define Bn      2
#define Tn      16384
#define Ln      64
#define HOPn    256
#define INCH    101
#define INNERC  128
#define CONDC   81
#define KHC     64
#define COUTC   256
#define KCHn    491520
#define BCHn    1280
#define WROW    264
#define SLICE_U32 50688         // 192*264 u32 per plane per slice

// ---------------- numeric helpers ----------------
__device__ __forceinline__ unsigned f2tf(float f) {
    unsigned u; asm("cvt.rna.tf32.f32 %0, %1;" : "=r"(u) : "f"(f)); return u;
}
__device__ __forceinline__ void split_tf(float v, float& hi, float& lo) {
    hi = __uint_as_float(f2tf(v));
    lo = __uint_as_float(f2tf(v - hi));
}
__device__ __forceinline__ void split_bf(float v, unsigned& h, unsigned& l) {
    __nv_bfloat16 hb = __float2bfloat16_rn(v);
    float hf = __bfloat162float(hb);
    __nv_bfloat16 lb = __float2bfloat16_rn(v - hf);
    h = (unsigned)__bfloat16_as_ushort(hb);
    l = (unsigned)__bfloat16_as_ushort(lb);
}
__device__ __forceinline__ void mma_tf32(float* d, const unsigned* a, const unsigned* b) {
    asm("mma.sync.aligned.m16n8k8.row.col.f32.tf32.tf32.f32 "
        "{%0,%1,%2,%3}, {%4,%5,%6,%7}, {%8,%9}, {%0,%1,%2,%3};"
        : "+f"(d[0]), "+f"(d[1]), "+f"(d[2]), "+f"(d[3])
        : "r"(a[0]), "r"(a[1]), "r"(a[2]), "r"(a[3]), "r"(b[0]), "r"(b[1]));
}
__device__ __forceinline__ void mma_bf16(float* d, const unsigned* a, const unsigned* b) {
    asm("mma.sync.aligned.m16n8k16.row.col.f32.bf16.bf16.f32 "
        "{%0,%1,%2,%3}, {%4,%5,%6,%7}, {%8,%9}, {%0,%1,%2,%3};"
        : "+f"(d[0]), "+f"(d[1]), "+f"(d[2]), "+f"(d[3])
        : "r"(a[0]), "r"(a[1]), "r"(a[2]), "r"(a[3]), "r"(b[0]), "r"(b[1]));
}
__device__ __forceinline__ void bulk_ld(unsigned dst_smem, const void* gsrc,
                                        unsigned bytes, unsigned mbar) {
    asm volatile("cp.async.bulk.shared::cta.global.mbarrier::complete_tx::bytes "
                 "[%0], [%1], %2, [%3];"
                 :: "r"(dst_smem), "l"(gsrc), "r"(bytes), "r"(mbar) : "memory");
}
__device__ __forceinline__ void mbar_init(unsigned mbar, unsigned cnt) {
    asm volatile("mbarrier.init.shared.b64 [%0], %1;" :: "r"(mbar), "r"(cnt) : "memory");
}
__device__ __forceinline__ void mbar_expect(unsigned mbar, unsigned bytes) {
    asm volatile("mbarrier.arrive.expect_tx.shared.b64 _, [%0], %1;"
                 :: "r"(mbar), "r"(bytes) : "memory");
}
__device__ __forceinline__ void mbar_wait(unsigned mbar, unsigned parity) {
    asm volatile(
        "{\n\t.reg .pred P1;\n\t"
        "WAIT_LOOP_%=:\n\t"
        "mbarrier.try_wait.parity.acquire.cta.shared::cta.b64 P1, [%0], %1, 0x989680;\n\t"
        "@P1 bra.uni WAIT_DONE_%=;\n\t"
        "bra.uni WAIT_LOOP_%=;\n\t"
        "WAIT_DONE_%=:\n\t}"
        :: "r"(mbar), "r"(parity) : "memory");
}

// ---------------- scratch ----------------
__device__ float    g_h [Bn*INNERC*Tn];
__device__ float    g_x1[Bn*INNERC*Tn];
__device__ float    g_y1[Bn*INNERC*Tn];
__device__ unsigned g_hph[Bn*64*Tn], g_hpl[Bn*64*Tn];
__device__ unsigned g_xph[Bn*64*Tn], g_xpl[Bn*64*Tn];
__device__ unsigned g_yph[Bn*64*Tn], g_ypl[Bn*64*Tn];
__device__ float    g_hc[2*Bn*KHC*Ln];
__device__ float    g_bs[2*Bn*BCHn*Ln];
__device__ float    g_Bth[2*64*128], g_Btl[2*64*128];
__device__ unsigned g_Wh[(size_t)1280*SLICE_U32];
__device__ unsigned g_Wl[(size_t)1280*SLICE_U32];

// =====================================================================
// 1) fc
// =====================================================================
__global__ void __launch_bounds__(128)
fc_kernel(const float* __restrict__ x,
          const float* __restrict__ W,
          const float* __restrict__ bias,
          float* __restrict__ out,
          unsigned* __restrict__ outh,
          unsigned* __restrict__ outl)
{
    __shared__ float sx[INCH*32];
    __shared__ float sW[128*33];
    const int b  = blockIdx.y;
    const int t0 = blockIdx.x * 32;
    const int tid = threadIdx.x;

    for (int p = tid; p < INCH*32; p += 128) {
        int c = p >> 5, j = p & 31;
        sx[p] = x[((size_t)(b*INCH + c))*Tn + t0 + j];
    }
    float acc[32];
    float bv = bias[tid];
#pragma unroll
    for (int j = 0; j < 32; j++) acc[j] = bv;

    for (int c0 = 0; c0 < INCH; c0 += 32) {
        int cmax = (INCH - c0) < 32 ? (INCH - c0) : 32;
        __syncthreads();
        for (int p = tid; p < 128*32; p += 128) {
            int o = p >> 5, cl = p & 31;
            if (cl < cmax) sW[o*33 + cl] = W[o*INCH + c0 + cl];
        }
        __syncthreads();
        for (int cl = 0; cl < cmax; cl++) {
            float w = sW[tid*33 + cl];
            const float* xr = &sx[(c0 + cl)*32];
#pragma unroll
            for (int j = 0; j < 32; j++) acc[j] += w * xr[j];
        }
    }
    float* o = &out[((size_t)(b*INNERC + tid))*Tn + t0];
#pragma unroll
    for (int j = 0; j < 32; j++) o[j] = acc[j];

    __syncthreads();
#pragma unroll
    for (int j = 0; j < 32; j++) sW[tid*33 + j] = acc[j];
    __syncthreads();
    for (int p = tid; p < 64*32; p += 128) {
        int jg = p >> 5, t = p & 31;
        unsigned h0,l0,h1,l1;
        split_bf(sW[(2*jg)*33 + t],   h0, l0);
        split_bf(sW[(2*jg+1)*33 + t], h1, l1);
        size_t idx = ((size_t)(b*64 + jg))*Tn + t0 + t;
        outh[idx] = h0 | (h1 << 16);
        outl[idx] = l0 | (l1 << 16);
    }
}

// =====================================================================
// 2) kernel predictor
// =====================================================================
__global__ void __launch_bounds__(256)
predictor_kernel(const float* __restrict__ cond,
                 const float* __restrict__ iW, const float* __restrict__ ib,
                 const float* __restrict__ r1W, const float* __restrict__ r1b,
                 const float* __restrict__ r2W, const float* __restrict__ r2b,
                 const float* __restrict__ bW,  const float* __restrict__ bb,
                 float* __restrict__ hc_out, float* __restrict__ bias_out,
                 float* __restrict__ Bth, float* __restrict__ Btl)
{
    __shared__ float bufc[CONDC*Ln];
    __shared__ float bufh[KHC*Ln];
    const int nb = blockIdx.x;
    const int n  = nb >> 1;
    const int b  = nb & 1;
    const int tid = threadIdx.x;
    const int NT = 256;

    for (int p = tid; p < CONDC*Ln; p += NT) bufc[p] = cond[b*CONDC*Ln + p];
    __syncthreads();

    for (int idx = tid; idx < KHC*Ln; idx += NT) {
        int kh = idx >> 6, l = idx & 63;
        float a = ib[n*KHC + kh];
        const float* wrow = &iW[(size_t)(n*KHC + kh)*CONDC*5];
        for (int cc = 0; cc < CONDC; cc++) {
#pragma unroll
            for (int k = 0; k < 5; k++) {
                int ll = l + k - 2;
                if (ll >= 0 && ll < Ln) a += bufc[cc*Ln + ll] * wrow[cc*5 + k];
            }
        }
        bufh[idx] = a >= 0.f ? a : 0.1f*a;
    }
    __syncthreads();

    for (int idx = tid; idx < KHC*Ln; idx += NT) {
        int o = idx >> 6, l = idx & 63;
        float a = r1b[n*KHC + o];
        const float* wr = &r1W[(size_t)(n*KHC + o)*KHC];
        for (int i = 0; i < KHC; i++) a += wr[i] * bufh[i*Ln + l];
        bufc[idx] = a >= 0.f ? a : 0.1f*a;
    }
    __syncthreads();

    for (int idx = tid; idx < KHC*Ln; idx += NT) {
        int o = idx >> 6, l = idx & 63;
        float a = r2b[n*KHC + o];
        const float* wr = &r2W[(size_t)(n*KHC + o)*KHC];
        for (int i = 0; i < KHC; i++) a += wr[i] * bufc[i*Ln + l];
        bufh[idx] = bufh[idx] + a;
    }
    __syncthreads();

    for (int idx = tid; idx < KHC*Ln; idx += NT) hc_out[nb*KHC*Ln + idx] = bufh[idx];

    for (int idx = tid; idx < KHC*Ln; idx += NT) {
        int k = idx >> 6, l = idx & 63;
        float h, lo; split_tf(bufh[k*Ln + l], h, lo);
        int col = b*64 + l;
        Bth[(n*64 + k)*128 + col] = h;
        Btl[(n*64 + k)*128 + col] = lo;
    }

    for (int idx = tid; idx < BCHn*Ln; idx += NT) {
        int j = idx >> 6, l = idx & 63;
        float a = bb[n*BCHn + j];
        const float* wr = &bW[(size_t)(n*BCHn + j)*KHC];
        for (int i = 0; i < KHC; i++) a += wr[i] * bufh[i*Ln + l];
        bias_out[(size_t)nb*BCHn*Ln + idx] = a;
    }
}

// =====================================================================
// 3) weight GEMM per slab nl (side stream) — A-tile register prefetch
// =====================================================================
#define WG_SA 4352
#define WG_SB 8704
#define WG_SMEM ((2*WG_SA + 2*WG_SB) * (int)sizeof(float))

__global__ void __launch_bounds__(256)
wgemm_kernel(const float* __restrict__ kW,
             const float* __restrict__ kb,
             const float* __restrict__ Bth,
             const float* __restrict__ Btl,
             unsigned* __restrict__ gWh,
             unsigned* __restrict__ gWl,
             int nl)
{
    extern __shared__ float wsm[];
    float* sAh = wsm;
    float* sAl = wsm + WG_SA;
    float* sBh = wsm + 2*WG_SA;
    float* sBl = wsm + 2*WG_SA + WG_SB;

    const int tid  = threadIdx.x;
    const int bx   = blockIdx.x;
    const int n    = nl / 5, layer = nl % 5;
    const int ip   = bx / 12;
    const int rem  = bx % 12;
    const int tap  = rem >> 2;
    const int o0   = (rem & 3) * 64;

    const size_t nbase = (size_t)n*KCHn + (size_t)layer*(384*256);
    const size_t srcrowE = nbase + (size_t)(2*ip)*768 + (size_t)o0*3 + tap;

    const float4* kW4 = (const float4*)kW;
    // per-thread A addresses: 4 iterations of p4 = tid + it*256
    int rr[4], kq[4];
#pragma unroll
    for (int it = 0; it < 4; it++) {
        int p4 = tid + it*256;
        rr[it] = p4 >> 4; kq[it] = p4 & 15;
    }
    // prefetch A(par=0)
    float4 apf[4];
#pragma unroll
    for (int it = 0; it < 4; it++)
        apf[it] = kW4[srcrowE*16 + (size_t)rr[it]*48 + kq[it]];

    // stage B (overlaps A prefetch latency)
    {
        const float4* srcH4 = (const float4*)(Bth + n*8192);
        const float4* srcL4 = (const float4*)(Btl + n*8192);
        for (int p4 = tid; p4 < 64*32; p4 += 256) {
            int k = p4 >> 5, c4 = p4 & 31;
            *(float4*)(sBh + k*136 + c4*4) = srcH4[p4];
            *(float4*)(sBl + k*136 + c4*4) = srcL4[p4];
        }
    }

    const int wid  = tid >> 5;
    const int lane = tid & 31;
    const int obase = (wid >> 2) * 32;
    const int cbase = (wid & 3) * 32;
    const int lr = lane >> 2;
    const int lc = lane & 3;

    // prefetch epilogue biases
    const float* kbE = kb + srcrowE;
    const float* kbO = kbE + 768;
    float kbv[2][4];
#pragma unroll
    for (int mt = 0; mt < 2; mt++) {
        int olo = obase + mt*16 + lr;
        kbv[mt][0] = kbE[(size_t)olo*3];
        kbv[mt][1] = kbO[(size_t)olo*3];
        kbv[mt][2] = kbE[(size_t)(olo+8)*3];
        kbv[mt][3] = kbO[(size_t)(olo+8)*3];
    }

    float d[2][2][4][4];
#pragma unroll
    for (int p = 0; p < 2; p++)
#pragma unroll
        for (int mt = 0; mt < 2; mt++)
#pragma unroll
            for (int nt = 0; nt < 4; nt++)
#pragma unroll
                for (int q = 0; q < 4; q++) d[p][mt][nt][q] = 0.f;

#pragma unroll
    for (int par = 0; par < 2; par++) {
        __syncthreads();
        // store prefetched A tile (split to hi/lo)
#pragma unroll
        for (int it = 0; it < 4; it++) {
            float h0,l0,h1,l1,h2,l2,h3,l3;
            split_tf(apf[it].x,h0,l0); split_tf(apf[it].y,h1,l1);
            split_tf(apf[it].z,h2,l2); split_tf(apf[it].w,h3,l3);
            float* dh = sAh + rr[it]*68 + kq[it]*4;
            float* dl = sAl + rr[it]*68 + kq[it]*4;
            dh[0]=h0; dh[1]=h1; dh[2]=h2; dh[3]=h3;
            dl[0]=l0; dl[1]=l1; dl[2]=l2; dl[3]=l3;
        }
        // prefetch A(par=1) — overlaps the par=0 compute below
        if (par == 0) {
            const size_t srcrow1 = srcrowE + 768;
#pragma unroll
            for (int it = 0; it < 4; it++)
                apf[it] = kW4[srcrow1*16 + (size_t)rr[it]*48 + kq[it]];
        }
        __syncthreads();

#pragma unroll
        for (int ks = 0; ks < 8; ks++) {
            unsigned bh[4][2], bl[4][2];
            const float* bpH = sBh + (ks*8 + lc)*136 + cbase + lr;
            const float* bpL = sBl + (ks*8 + lc)*136 + cbase + lr;
#pragma unroll
            for (int nt = 0; nt < 4; nt++) {
                bh[nt][0] = __float_as_uint(bpH[nt*8]);
                bh[nt][1] = __float_as_uint(bpH[4*136 + nt*8]);
                bl[nt][0] = __float_as_uint(bpL[nt*8]);
                bl[nt][1] = __float_as_uint(bpL[4*136 + nt*8]);
            }
#pragma unroll
            for (int mt = 0; mt < 2; mt++) {
                const int ap = (obase + mt*16 + lr)*68 + ks*8 + lc;
                unsigned ah[4], al[4];
                ah[0] = __float_as_uint(sAh[ap]);
                ah[1] = __float_as_uint(sAh[ap + 8*68]);
                ah[2] = __float_as_uint(sAh[ap + 4]);
                ah[3] = __float_as_uint(sAh[ap + 8*68 + 4]);
                al[0] = __float_as_uint(sAl[ap]);
                al[1] = __float_as_uint(sAl[ap + 8*68]);
                al[2] = __float_as_uint(sAl[ap + 4]);
                al[3] = __float_as_uint(sAl[ap + 8*68 + 4]);
#pragma unroll
                for (int nt = 0; nt < 4; nt++) {
                    mma_tf32(d[par][mt][nt], ah, bh[nt]);
                    mma_tf32(d[par][mt][nt], al, bh[nt]);
                    mma_tf32(d[par][mt][nt], ah, bl[nt]);
                }
            }
        }
    }

    __syncthreads();
    unsigned* sDh = (unsigned*)wsm;
    unsigned* sDl = sDh + 128*68;
#pragma unroll
    for (int mt = 0; mt < 2; mt++) {
        int olo = obase + mt*16 + lr;
        float beL = kbv[mt][0], boL = kbv[mt][1];
        float beH = kbv[mt][2], boH = kbv[mt][3];
#pragma unroll
        for (int nt = 0; nt < 4; nt++) {
#pragma unroll
            for (int q = 0; q < 4; q++) {
                int col = cbase + nt*8 + 2*lc + (q & 1);
                int oE  = (q < 2) ? olo : olo + 8;
                float ve = d[0][mt][nt][q] + ((q < 2) ? beL : beH);
                float vo = d[1][mt][nt][q] + ((q < 2) ? boL : boH);
                unsigned he, le, ho, lo2;
                split_bf(ve, he, le);
                split_bf(vo, ho, lo2);
                sDh[col*68 + oE] = he | (ho << 16);
                sDl[col*68 + oE] = le | (lo2 << 16);
            }
        }
    }
    __syncthreads();
    const size_t jrowp = (size_t)(tap*64 + ip)*WROW + o0;
    uint4* gH4 = (uint4*)gWh;
    uint4* gL4 = (uint4*)gWl;
    for (int p = tid; p < 128*16; p += 256) {
        int col = p >> 4, o4 = p & 15;
        size_t adr4 = ((size_t)(nl*128 + col)*SLICE_U32 + jrowp)/4 + o4;
        gH4[adr4] = *(uint4*)(sDh + col*68 + o4*4);
        gL4[adr4] = *(uint4*)(sDl + col*68 + o4*4);
    }
}

// =====================================================================
// 4) LVC layer: bf16 3-term mma, bulk-TMA pipeline, TMA issued before
//    x staging so staging overlaps the first DRAM round trips.
// =====================================================================
#define XSTR 168
#define LVC_XPL (64*XSTR)
#define LVC_WPL (16*WROW)
#define CHUNK_BYTES (LVC_WPL*4)
#define LVC_SMEM ((2*LVC_XPL + 8*LVC_WPL + 256)*4)   // 222208 B

template<int D>
__global__ void __launch_bounds__(512, 1)
lvc_kernel(const unsigned* __restrict__ inh, const unsigned* __restrict__ inl,
           float* __restrict__ xout,
           unsigned* __restrict__ outh, unsigned* __restrict__ outl,
           const unsigned* __restrict__ gWh, const unsigned* __restrict__ gWl,
           const float* __restrict__ gbias,
           int n, int layer, int accflag)
{
    extern __shared__ unsigned smu[];
    __shared__ unsigned long long s_mbar[4];
    unsigned* xph = smu;
    unsigned* xpl = smu + LVC_XPL;
    unsigned* wbase_ = smu + 2*LVC_XPL;
    float* sbias  = (float*)(wbase_ + 8*LVC_WPL);

    const int hf  = blockIdx.x;
    const int l   = blockIdx.y;
    const int b   = blockIdx.z;
    const int tid = threadIdx.x;
    const int wid = tid >> 5;
    const int lane = tid & 31;
    const int og = wid >> 2;
    const int obase = og * 64;
    const int sbase = (wid & 3) * 32;
    const int lr = lane >> 2;
    const int lc = lane & 3;

    const int t_base = l*HOPn + hf*128;
    const int win = 128 + 2*D;

    const size_t slice = (size_t)((n*5 + layer)*128 + b*64 + l)*SLICE_U32;
    const char* srcH = (const char*)(gWh + slice);
    const char* srcL = (const char*)(gWl + slice);
    const unsigned mbar0 = (unsigned)__cvta_generic_to_shared(s_mbar);
    const unsigned wsm0  = (unsigned)__cvta_generic_to_shared(wbase_);

    // init mbars, make visible, issue prologue TMA FIRST
    if (tid == 0) {
#pragma unroll
        for (int i = 0; i < 4; i++) mbar_init(mbar0 + i*8, 1);
    }
    __syncthreads();
    if (tid == 0) {
#pragma unroll
        for (int cc = 0; cc < 3; cc++) {
            unsigned mb = mbar0 + (cc & 3)*8;
            unsigned dst = wsm0 + (cc & 3)*2*CHUNK_BYTES;
            mbar_expect(mb, 2*CHUNK_BYTES);
            bulk_ld(dst,               srcH + (size_t)cc*CHUNK_BYTES, CHUNK_BYTES, mb);
            bulk_ld(dst + CHUNK_BYTES, srcL + (size_t)cc*CHUNK_BYTES, CHUNK_BYTES, mb);
        }
    }

    // x staging overlaps the in-flight TMA
    for (int p = tid; p < 64*win; p += 512) {
        int jg = p / win;
        int j  = p - jg*win;
        int t  = t_base - D + j;
        unsigned vh = 0, vl = 0;
        if (t >= 0 && t < Tn) {
            size_t idx = ((size_t)(b*64 + jg))*Tn + t;
            vh = inh[idx]; vl = inl[idx];
        }
        xph[jg*XSTR + j] = vh;
        xpl[jg*XSTR + j] = vl;
    }
    if (tid < 256)
        sbias[tid] = gbias[(size_t)(((n*2 + b)*BCHn) + layer*COUTC + tid)*Ln + l];
    __syncthreads();

    float d[4][4][4];
#pragma unroll
    for (int mt = 0; mt < 4; mt++) {
        int olo = obase + mt*16 + lr;
        float blo = sbias[olo], bhi = sbias[olo + 8];
#pragma unroll
        for (int nt = 0; nt < 4; nt++) {
            d[mt][nt][0] = blo; d[mt][nt][1] = blo;
            d[mt][nt][2] = bhi; d[mt][nt][3] = bhi;
        }
    }

#pragma unroll
    for (int c = 0; c < 12; c++) {
        mbar_wait(mbar0 + (c & 3)*8, (c >> 2) & 1);

        const unsigned* bh_ = wbase_ + (c & 3)*2*LVC_WPL;
        const unsigned* bl_ = bh_ + LVC_WPL;
        const int tap  = c >> 2;
        const int toff = tap * D;
        const int jrow0 = (c & 3) * 16;

#pragma unroll
        for (int ks = 0; ks < 2; ks++) {
            unsigned bh[4][2], bl[4][2];
            const unsigned* bpH = xph + (jrow0 + ks*8 + lc)*XSTR + toff + sbase + lr;
            const unsigned* bpL = xpl + (jrow0 + ks*8 + lc)*XSTR + toff + sbase + lr;
#pragma unroll
            for (int nt = 0; nt < 4; nt++) {
                bh[nt][0] = bpH[nt*8];
                bh[nt][1] = bpH[4*XSTR + nt*8];
                bl[nt][0] = bpL[nt*8];
                bl[nt][1] = bpL[4*XSTR + nt*8];
            }
#pragma unroll
            for (int mt = 0; mt < 4; mt++) {
                const int ap = (ks*8 + lc)*WROW + obase + mt*16 + lr;
                unsigned ah[4], al[4];
                ah[0] = bh_[ap];            ah[1] = bh_[ap + 8];
                ah[2] = bh_[ap + 4*WROW];   ah[3] = bh_[ap + 4*WROW + 8];
                al[0] = bl_[ap];            al[1] = bl_[ap + 8];
                al[2] = bl_[ap + 4*WROW];   al[3] = bl_[ap + 4*WROW + 8];
#pragma unroll
                for (int nt = 0; nt < 4; nt++) {
                    mma_bf16(d[mt][nt], ah, bh[nt]);
                    mma_bf16(d[mt][nt], al, bh[nt]);
                    mma_bf16(d[mt][nt], ah, bl[nt]);
                }
            }
        }

        __syncthreads();
        if (c < 9 && tid == 0) {
            int cc = c + 3;
            unsigned mb = mbar0 + (cc & 3)*8;
            unsigned dst = wsm0 + (cc & 3)*2*CHUNK_BYTES;
            mbar_expect(mb, 2*CHUNK_BYTES);
            bulk_ld(dst,               srcH + (size_t)cc*CHUNK_BYTES, CHUNK_BYTES, mb);
            bulk_ld(dst + CHUNK_BYTES, srcL + (size_t)cc*CHUNK_BYTES, CHUNK_BYTES, mb);
        }
    }
    __syncthreads();

    float* ys2 = (float*)smu;
    float* ys3 = (float*)(smu + 2*LVC_XPL);

    if (og >= 2) {
#pragma unroll
        for (int mt = 0; mt < 4; mt++) {
            int ro = (og - 2)*64 + mt*16 + lr;
#pragma unroll
            for (int nt = 0; nt < 4; nt++) {
                int s = sbase + nt*8 + 2*lc;
                ys2[ro*133 + s]       = d[mt][nt][0];
                ys2[ro*133 + s + 1]   = d[mt][nt][1];
                ys2[(ro+8)*133 + s]   = d[mt][nt][2];
                ys2[(ro+8)*133 + s+1] = d[mt][nt][3];
            }
        }
    }
    __syncthreads();
    if (og < 2) {
#pragma unroll
        for (int mt = 0; mt < 4; mt++) {
#pragma unroll
            for (int q2 = 0; q2 < 2; q2++) {
                int o = obase + mt*16 + lr + q2*8;
#pragma unroll
                for (int nt = 0; nt < 4; nt++) {
#pragma unroll
                    for (int qp = 0; qp < 2; qp++) {
                        int s = sbase + nt*8 + 2*lc + qp;
                        float lov = d[mt][nt][q2*2 + qp];
                        float hiv = ys2[o*133 + s];
                        ys3[o*132 + s] = tanhf(hiv) / (1.f + __expf(-lov));
                    }
                }
            }
        }
    }
    __syncthreads();

    for (int idx = tid; idx < 128*32; idx += 512) {
        int o = idx >> 5, s4 = (idx & 31)*4;
        float4 v = *(float4*)(ys3 + o*132 + s4);
        float4* dp = (float4*)(xout + ((size_t)(b*INNERC + o))*Tn + t_base + s4);
        if (accflag) {
            float4 old = *dp;
            v.x += old.x; v.y += old.y; v.z += old.z; v.w += old.w;
            *(float4*)(ys3 + o*132 + s4) = v;
        }
        *dp = v;
    }
    if (accflag) __syncthreads();
    for (int idx = tid; idx < 64*128; idx += 512) {
        int jg = idx >> 7, s = idx & 127;
        unsigned h0,l0,h1,l1;
        split_bf(ys3[(2*jg)*132 + s],   h0, l0);
        split_bf(ys3[(2*jg+1)*132 + s], h1, l1);
        size_t gidx = ((size_t)(b*64 + jg))*Tn + t_base + s;
        outh[gidx] = h0 | (h1 << 16);
        outl[gidx] = l0 | (l1 << 16);
    }
}

// =====================================================================
// 5) final
// =====================================================================
__global__ void __launch_bounds__(128)
final_kernel(const float* __restrict__ h,
             const float* __restrict__ W1, const float* __restrict__ b1,
             const float* __restrict__ W2, const float* __restrict__ b2,
             float* __restrict__ out)
{
    __shared__ float bufA[64*129];
    __shared__ float bufB[64*32];
    const int b  = blockIdx.y;
    const int t0 = blockIdx.x * 32;
    const int tid = threadIdx.x;

    float acc[32];
    float bv = b1[tid];
#pragma unroll
    for (int j = 0; j < 32; j++) acc[j] = bv;

    for (int c0 = 0; c0 < 128; c0 += 64) {
        __syncthreads();
        for (int p = tid; p < 128*64; p += 128) {
            int o = p >> 6, cl = p & 63;
            bufA[cl*129 + o] = W1[o*128 + c0 + cl];
        }
        for (int p = tid; p < 64*32; p += 128) {
            int cl = p >> 5, j = p & 31;
            float v = h[((size_t)(b*INNERC + c0 + cl))*Tn + t0 + j];
            bufB[p] = v > 0.f ? v : 0.f;
        }
        __syncthreads();
        for (int cl = 0; cl < 64; cl++) {
            float w = bufA[cl*129 + tid];
            const float* xr = &bufB[cl*32];
#pragma unroll
            for (int j = 0; j < 32; j++) acc[j] += w * xr[j];
        }
    }
    __syncthreads();
#pragma unroll
    for (int j = 0; j < 32; j++) bufA[tid*33 + j] = acc[j] > 0.f ? acc[j] : 0.f;
    __syncthreads();
    if (tid < 32) {
        float s = b2[0];
        for (int o = 0; o < 128; o++) s += W2[o] * bufA[o*33 + tid];
        out[(size_t)b*Tn + t0 + tid] = s;
    }
}

// =====================================================================
// launcher — R11 structure: wgemm slabs on side stream, event-chained
// =====================================================================
extern "C" void kernel_launch(void* const* d_in, const int* in_sizes, int n_in,
                              void* d_out, int out_size)
{
    (void)in_sizes; (void)n_in; (void)out_size;
    const float* x      = (const float*)d_in[0];
    const float* cnd    = (const float*)d_in[1];
    const float* fc_W   = (const float*)d_in[2];
    const float* fc_b   = (const float*)d_in[3];
    const float* inp_W  = (const float*)d_in[4];
    const float* inp_b  = (const float*)d_in[5];
    const float* res1_W = (const float*)d_in[6];
    const float* res1_b = (const float*)d_in[7];
    const float* res2_W = (const float*)d_in[8];
    const float* res2_b = (const float*)d_in[9];
    const float* kern_W = (const float*)d_in[10];
    const float* kern_b = (const float*)d_in[11];
    const float* bc_W   = (const float*)d_in[12];
    const float* bc_b   = (const float*)d_in[13];
    const float* lc1_W  = (const float*)d_in[14];
    const float* lc1_b  = (const float*)d_in[15];
    const float* lc2_W  = (const float*)d_in[16];
    const float* lc2_b  = (const float*)d_in[17];
    float* out = (float*)d_out;

    float *h, *xb, *yb, *hc, *bs, *Bth, *Btl;
    unsigned *hph,*hpl,*xph,*xpl,*yph,*ypl,*Wh,*Wl;
    cudaGetSymbolAddress((void**)&h,  g_h);
    cudaGetSymbolAddress((void**)&xb, g_x1);
    cudaGetSymbolAddress((void**)&yb, g_y1);
    cudaGetSymbolAddress((void**)&hc, g_hc);
    cudaGetSymbolAddress((void**)&bs, g_bs);
    cudaGetSymbolAddress((void**)&Bth, g_Bth);
    cudaGetSymbolAddress((void**)&Btl, g_Btl);
    cudaGetSymbolAddress((void**)&hph, g_hph);
    cudaGetSymbolAddress((void**)&hpl, g_hpl);
    cudaGetSymbolAddress((void**)&xph, g_xph);
    cudaGetSymbolAddress((void**)&xpl, g_xpl);
    cudaGetSymbolAddress((void**)&yph, g_yph);
    cudaGetSymbolAddress((void**)&ypl, g_ypl);
    cudaGetSymbolAddress((void**)&Wh, g_Wh);
    cudaGetSymbolAddress((void**)&Wl, g_Wl);

    static cudaStream_t s_side = nullptr;
    static cudaEvent_t  s_fork = nullptr;
    static cudaEvent_t  s_slab[10];
    static bool s_attr = false;
    if (!s_side) {
        cudaStreamCreateWithFlags(&s_side, cudaStreamNonBlocking);
        cudaEventCreateWithFlags(&s_fork, cudaEventDisableTiming);
        for (int i = 0; i < 10; i++)
            cudaEventCreateWithFlags(&s_slab[i], cudaEventDisableTiming);
    }
    if (!s_attr) {
        cudaFuncSetAttribute(wgemm_kernel,   cudaFuncAttributeMaxDynamicSharedMemorySize, WG_SMEM);
        cudaFuncSetAttribute(lvc_kernel<1>,  cudaFuncAttributeMaxDynamicSharedMemorySize, LVC_SMEM);
        cudaFuncSetAttribute(lvc_kernel<2>,  cudaFuncAttributeMaxDynamicSharedMemorySize, LVC_SMEM);
        cudaFuncSetAttribute(lvc_kernel<4>,  cudaFuncAttributeMaxDynamicSharedMemorySize, LVC_SMEM);
        cudaFuncSetAttribute(lvc_kernel<8>,  cudaFuncAttributeMaxDynamicSharedMemorySize, LVC_SMEM);
        cudaFuncSetAttribute(lvc_kernel<16>, cudaFuncAttributeMaxDynamicSharedMemorySize, LVC_SMEM);
        s_attr = true;
    }

    predictor_kernel<<<4, 256>>>(cnd, inp_W, inp_b, res1_W, res1_b,
                                 res2_W, res2_b, bc_W, bc_b, hc, bs, Bth, Btl);
    cudaEventRecord(s_fork, 0);
    cudaStreamWaitEvent(s_side, s_fork, 0);

    for (int nl = 0; nl < 10; nl++) {
        wgemm_kernel<<<768, 256, WG_SMEM, s_side>>>(kern_W, kern_b, Bth, Btl, Wh, Wl, nl);
        cudaEventRecord(s_slab[nl], s_side);
    }

    fc_kernel<<<dim3(Tn/32, Bn), 128>>>(x, fc_W, fc_b, h, hph, hpl);

    for (int n = 0; n < 2; n++) {
        const unsigned *cih = hph, *cil = hpl;
        for (int i = 0; i < 5; i++) {
            float* outf; unsigned *oh, *ol;
            if (i == 4)      { outf = h;  oh = hph; ol = hpl; }
            else if (i & 1)  { outf = yb; oh = yph; ol = ypl; }
            else             { outf = xb; oh = xph; ol = xpl; }
            int accfl = (i == 4 && n == 1) ? 1 : 0;
            cudaStreamWaitEvent(0, s_slab[n*5 + i], 0);
            dim3 g(2, Ln, Bn);
            switch (i) {
                case 0: lvc_kernel<1> <<<g, 512, LVC_SMEM>>>(cih, cil, outf, oh, ol, Wh, Wl, bs, n, i, accfl); break;
                case 1: lvc_kernel<2> <<<g, 512, LVC_SMEM>>>(cih, cil, outf, oh, ol, Wh, Wl, bs, n, i, accfl); break;
                case 2: lvc_kernel<4> <<<g, 512, LVC_SMEM>>>(cih, cil, outf, oh, ol, Wh, Wl, bs, n, i, accfl); break;
                case 3: lvc_kernel<8> <<<g, 512, LVC_SMEM>>>(cih, cil, outf, oh, ol, Wh, Wl, bs, n, i, accfl); break;
                case 4: lvc_kernel<16><<<g, 512, LVC_SMEM>>>(cih, cil, outf, oh, ol, Wh, Wl, bs, n, i, accfl); break;
            }
            cih = oh; cil = ol;
        }
    }

    final_kernel<<<dim3(Tn/32, Bn), 128>>>(h, lc1_W, lc1_b, lc2_W, lc2_b, out);
}